// round 2
// baseline (speedup 1.0000x reference)
#include <cuda_runtime.h>

#define Bb    32
#define Ff    128
#define Hh    256
#define Nn    2048
#define Ll    2
#define Ee    262144
#define NNODE 65536   // B*N

// ---------------- scratch (device globals; no allocation allowed) ----------
__device__ float g_h0buf[(size_t)NNODE * Hh];
__device__ float g_h1buf[(size_t)NNODE * Hh];
__device__ float g_Abuf [(size_t)NNODE * Hh];
__device__ float g_Bbuf [(size_t)NNODE * Hh];
__device__ float g_agg  [(size_t)NNODE * Hh];
__device__ float g_pos  [(size_t)NNODE * 3];
__device__ float g_pacc [(size_t)NNODE * 3];
__device__ float g_hb   [Bb * Hh];
__device__ float g_gf   [Nn * Hh];
__device__ float g_md   [Nn];

// ---------------- small prologue kernels -----------------------------------

// per-batch base embedding: hb[b][j] = sum_k x[b][k] * W_in[k][j] + b_in[j]
__global__ void k_hbase(const float* __restrict__ x, const float* __restrict__ W_in,
                        const float* __restrict__ b_in) {
    __shared__ float xb[Ff];
    int b = blockIdx.x;
    if (threadIdx.x < Ff) xb[threadIdx.x] = x[b * Ff + threadIdx.x];
    __syncthreads();
    int j = threadIdx.x;
    float acc = b_in[j];
    #pragma unroll 4
    for (int k = 0; k < Ff; k++) acc = fmaf(xb[k], W_in[k * Hh + j], acc);
    g_hb[b * Hh + j] = acc;
}

// mean pairwise distance per point
__global__ void k_meand(const float* __restrict__ positions) {
    __shared__ float sp[Nn * 3];
    __shared__ float red[256];
    int i = blockIdx.x;
    for (int t = threadIdx.x; t < Nn * 3; t += 256) sp[t] = positions[t];
    __syncthreads();
    float px = sp[i * 3], py = sp[i * 3 + 1], pz = sp[i * 3 + 2];
    float sum = 0.f;
    for (int j = threadIdx.x; j < Nn; j += 256) {
        if (j == i) continue;
        float dx = px - sp[j * 3], dy = py - sp[j * 3 + 1], dz = pz - sp[j * 3 + 2];
        sum += sqrtf(dx * dx + dy * dy + dz * dz);
    }
    red[threadIdx.x] = sum;
    __syncthreads();
    for (int s = 128; s; s >>= 1) {
        if (threadIdx.x < s) red[threadIdx.x] += red[threadIdx.x + s];
        __syncthreads();
    }
    if (threadIdx.x == 0) g_md[i] = red[0] / (float)(Nn - 1);
}

// geometric feature MLP: gf[n] = relu([m,m,m] @ Wg1 + bg1) @ Wg2 + bg2
__global__ void k_gfeat(const float* __restrict__ Wg1, const float* __restrict__ bg1,
                        const float* __restrict__ Wg2, const float* __restrict__ bg2) {
    __shared__ float t[Ff];  // H/2 = 128
    int n = blockIdx.x;
    float m = g_md[n];
    if (threadIdx.x < 128) {
        int kk = threadIdx.x;
        float w = Wg1[kk] + Wg1[128 + kk] + Wg1[256 + kk];
        t[kk] = fmaxf(fmaf(m, w, bg1[kk]), 0.f);
    }
    __syncthreads();
    int j = threadIdx.x;
    float acc = bg2[j];
    #pragma unroll 4
    for (int kk = 0; kk < 128; kk++) acc = fmaf(t[kk], Wg2[kk * Hh + j], acc);
    g_gf[n * Hh + j] = acc;
}

// h[b*N+n][j] = hb[b][j] + gf[n][j]; also init pos broadcast
__global__ void k_init(const float* __restrict__ positions) {
    int i = blockIdx.x * 256 + threadIdx.x;  // over NNODE*Hh
    int node = i >> 8, j = i & 255;
    int b = node >> 11;       // /2048
    int n = node & 2047;
    g_h0buf[i] = g_hb[b * Hh + j] + g_gf[n * Hh + j];
    if (i < NNODE * 3) {
        int nd = i / 3;
        int k = i - nd * 3;
        g_pos[i] = positions[(nd & 2047) * 3 + k];
    }
}

__global__ void k_zero_agg() {
    int i = blockIdx.x * 256 + threadIdx.x;
    ((float4*)g_agg)[i] = make_float4(0.f, 0.f, 0.f, 0.f);
    if (i < NNODE * 3 / 4) ((float4*)g_pacc)[i] = make_float4(0.f, 0.f, 0.f, 0.f);
}

__global__ void k_posapply() {
    int i = blockIdx.x * 256 + threadIdx.x;
    if (i < NNODE * 3) g_pos[i] += g_pacc[i] * 0.25f;  // 1/DEG, DEG=4
}

// ---------------- GEMMs (fp32 SIMT, 128x128x16, 8x8/thread) ----------------

// C[M=NNODE, 256] = X[M,256] @ W[256,256]   (W row-major [K,N])
__global__ __launch_bounds__(256, 2) void k_gemm_proj(const float* __restrict__ X,
                                                      const float* __restrict__ W,
                                                      float* __restrict__ C) {
    __shared__ float As[16][128];
    __shared__ float Bs[16][128];
    const int row0 = blockIdx.y * 128;
    const int col0 = blockIdx.x * 128;
    const int tid = threadIdx.x;
    const int ty = (tid >> 4) << 3;
    const int tx = (tid & 15) << 3;
    float acc[8][8];
    #pragma unroll
    for (int i = 0; i < 8; i++)
        #pragma unroll
        for (int j = 0; j < 8; j++) acc[i][j] = 0.f;

    for (int k0 = 0; k0 < 256; k0 += 16) {
        #pragma unroll
        for (int i = 0; i < 2; i++) {
            int fi = tid * 2 + i;
            int r = fi >> 2, c = (fi & 3) << 2;
            float4 v = *(const float4*)(X + (size_t)(row0 + r) * 256 + k0 + c);
            As[c][r] = v.x; As[c + 1][r] = v.y; As[c + 2][r] = v.z; As[c + 3][r] = v.w;
        }
        #pragma unroll
        for (int i = 0; i < 2; i++) {
            int fi = tid * 2 + i;
            int r = fi >> 5, c = (fi & 31) << 2;
            *(float4*)&Bs[r][c] = *(const float4*)(W + (size_t)(k0 + r) * 256 + col0 + c);
        }
        __syncthreads();
        #pragma unroll
        for (int k = 0; k < 16; k++) {
            float ra[8], rb[8];
            #pragma unroll
            for (int i = 0; i < 8; i++) ra[i] = As[k][ty + i];
            #pragma unroll
            for (int j = 0; j < 8; j++) rb[j] = Bs[k][tx + j];
            #pragma unroll
            for (int i = 0; i < 8; i++)
                #pragma unroll
                for (int j = 0; j < 8; j++) acc[i][j] = fmaf(ra[i], rb[j], acc[i][j]);
        }
        __syncthreads();
    }
    #pragma unroll
    for (int i = 0; i < 8; i++) {
        float* cr = C + (size_t)(row0 + ty + i) * 256 + col0 + tx;
        *(float4*)cr       = make_float4(acc[i][0], acc[i][1], acc[i][2], acc[i][3]);
        *(float4*)(cr + 4) = make_float4(acc[i][4], acc[i][5], acc[i][6], acc[i][7]);
    }
}

// Hout = Xh + relu( concat(Xh, Xa=g_agg) @ W[512,256] + bias )
__global__ __launch_bounds__(256, 2) void k_gemm_update(const float* __restrict__ Xh,
                                                        const float* __restrict__ W,
                                                        const float* __restrict__ bias,
                                                        float* __restrict__ Hout) {
    __shared__ float As[16][128];
    __shared__ float Bs[16][128];
    const int row0 = blockIdx.y * 128;
    const int col0 = blockIdx.x * 128;
    const int tid = threadIdx.x;
    const int ty = (tid >> 4) << 3;
    const int tx = (tid & 15) << 3;
    float acc[8][8];
    #pragma unroll
    for (int i = 0; i < 8; i++)
        #pragma unroll
        for (int j = 0; j < 8; j++) acc[i][j] = 0.f;

    for (int k0 = 0; k0 < 512; k0 += 16) {
        const float* Xs = (k0 < 256) ? Xh : (const float*)g_agg;
        int kk = k0 & 255;
        #pragma unroll
        for (int i = 0; i < 2; i++) {
            int fi = tid * 2 + i;
            int r = fi >> 2, c = (fi & 3) << 2;
            float4 v = *(const float4*)(Xs + (size_t)(row0 + r) * 256 + kk + c);
            As[c][r] = v.x; As[c + 1][r] = v.y; As[c + 2][r] = v.z; As[c + 3][r] = v.w;
        }
        #pragma unroll
        for (int i = 0; i < 2; i++) {
            int fi = tid * 2 + i;
            int r = fi >> 5, c = (fi & 31) << 2;
            *(float4*)&Bs[r][c] = *(const float4*)(W + (size_t)(k0 + r) * 256 + col0 + c);
        }
        __syncthreads();
        #pragma unroll
        for (int k = 0; k < 16; k++) {
            float ra[8], rb[8];
            #pragma unroll
            for (int i = 0; i < 8; i++) ra[i] = As[k][ty + i];
            #pragma unroll
            for (int j = 0; j < 8; j++) rb[j] = Bs[k][tx + j];
            #pragma unroll
            for (int i = 0; i < 8; i++)
                #pragma unroll
                for (int j = 0; j < 8; j++) acc[i][j] = fmaf(ra[i], rb[j], acc[i][j]);
        }
        __syncthreads();
    }
    #pragma unroll
    for (int i = 0; i < 8; i++) {
        size_t roff = (size_t)(row0 + ty + i) * 256 + col0 + tx;
        #pragma unroll
        for (int j = 0; j < 8; j++) {
            float v = acc[i][j] + bias[col0 + tx + j];
            v = fmaxf(v, 0.f);
            acc[i][j] = Xh[roff + j] + v;
        }
        float* cr = Hout + roff;
        *(float4*)cr       = make_float4(acc[i][0], acc[i][1], acc[i][2], acc[i][3]);
        *(float4*)(cr + 4) = make_float4(acc[i][4], acc[i][5], acc[i][6], acc[i][7]);
    }
}

// ---------------- edge kernel: 1 warp / edge --------------------------------
// m_j = relu(A[s][j] + B[t][j] + d*wd[j] + bm[j])
// agg[t] += m; coef = m . wp; pacc[t] += (pos[t]-pos[s]) * coef
__global__ __launch_bounds__(256) void k_edge(const int* __restrict__ ei,
                                              const float* __restrict__ wd,
                                              const float* __restrict__ bmv,
                                              const float* __restrict__ wp) {
    int e = (blockIdx.x << 3) + (threadIdx.x >> 5);
    int lane = threadIdx.x & 31;
    int s = __ldg(ei + e);
    int t = __ldg(ei + Ee + e);

    const float* pos = g_pos;
    float psx = pos[s * 3], psy = pos[s * 3 + 1], psz = pos[s * 3 + 2];
    float ptx = pos[t * 3], pty = pos[t * 3 + 1], ptz = pos[t * 3 + 2];
    float dx = psx - ptx, dy = psy - pty, dz = psz - ptz;
    float d = sqrtf(dx * dx + dy * dy + dz * dz + 1e-12f);

    int j0 = lane << 3;
    const float4* A4 = (const float4*)(g_Abuf + ((size_t)s << 8) + j0);
    const float4* B4 = (const float4*)(g_Bbuf + ((size_t)t << 8) + j0);
    float4 a0 = A4[0], a1 = A4[1];
    float4 b0 = B4[0], b1 = B4[1];
    float4 w0 = *(const float4*)(wd + j0),  w1 = *(const float4*)(wd + j0 + 4);
    float4 c0 = *(const float4*)(bmv + j0), c1 = *(const float4*)(bmv + j0 + 4);
    float4 p0 = *(const float4*)(wp + j0),  p1 = *(const float4*)(wp + j0 + 4);

    float4 m0, m1;
    m0.x = fmaxf(fmaf(d, w0.x, a0.x + b0.x + c0.x), 0.f);
    m0.y = fmaxf(fmaf(d, w0.y, a0.y + b0.y + c0.y), 0.f);
    m0.z = fmaxf(fmaf(d, w0.z, a0.z + b0.z + c0.z), 0.f);
    m0.w = fmaxf(fmaf(d, w0.w, a0.w + b0.w + c0.w), 0.f);
    m1.x = fmaxf(fmaf(d, w1.x, a1.x + b1.x + c1.x), 0.f);
    m1.y = fmaxf(fmaf(d, w1.y, a1.y + b1.y + c1.y), 0.f);
    m1.z = fmaxf(fmaf(d, w1.z, a1.z + b1.z + c1.z), 0.f);
    m1.w = fmaxf(fmaf(d, w1.w, a1.w + b1.w + c1.w), 0.f);

    float cf = m0.x * p0.x + m0.y * p0.y + m0.z * p0.z + m0.w * p0.w
             + m1.x * p1.x + m1.y * p1.y + m1.z * p1.z + m1.w * p1.w;

    float* ag = g_agg + ((size_t)t << 8) + j0;
    asm volatile("red.global.add.v4.f32 [%0], {%1,%2,%3,%4};"
                 :: "l"(ag), "f"(m0.x), "f"(m0.y), "f"(m0.z), "f"(m0.w) : "memory");
    asm volatile("red.global.add.v4.f32 [%0], {%1,%2,%3,%4};"
                 :: "l"(ag + 4), "f"(m1.x), "f"(m1.y), "f"(m1.z), "f"(m1.w) : "memory");

    #pragma unroll
    for (int off = 16; off; off >>= 1) cf += __shfl_xor_sync(0xffffffffu, cf, off);

    if (lane < 3) {
        float pd = (lane == 0) ? (ptx - psx) : (lane == 1) ? (pty - psy) : (ptz - psz);
        atomicAdd(g_pacc + (size_t)t * 3 + lane, pd * cf);
    }
}

// ---------------- output GEMV ----------------------------------------------
__global__ void k_out(const float* __restrict__ h, const float* __restrict__ Wout,
                      const float* __restrict__ bout, float* __restrict__ out) {
    int warp = (blockIdx.x * blockDim.x + threadIdx.x) >> 5;
    int lane = threadIdx.x & 31;
    if (warp >= NNODE) return;
    const float4* h4 = (const float4*)(h + (size_t)warp * 256);
    const float4* w4 = (const float4*)Wout;
    float acc = 0.f;
    float4 a = h4[lane * 2], b = w4[lane * 2];
    acc += a.x * b.x + a.y * b.y + a.z * b.z + a.w * b.w;
    a = h4[lane * 2 + 1]; b = w4[lane * 2 + 1];
    acc += a.x * b.x + a.y * b.y + a.z * b.z + a.w * b.w;
    #pragma unroll
    for (int off = 16; off; off >>= 1) acc += __shfl_xor_sync(0xffffffffu, acc, off);
    if (lane == 0) out[warp] = acc + bout[0];
}

// ---------------- launch ----------------------------------------------------
extern "C" void kernel_launch(void* const* d_in, const int* in_sizes, int n_in,
                              void* d_out, int out_size) {
    const float* x         = (const float*)d_in[0];
    const float* positions = (const float*)d_in[1];
    const float* W_in      = (const float*)d_in[2];
    const float* b_in      = (const float*)d_in[3];
    const float* Wg1       = (const float*)d_in[4];
    const float* bg1       = (const float*)d_in[5];
    const float* Wg2       = (const float*)d_in[6];
    const float* bg2       = (const float*)d_in[7];
    const float* Wm        = (const float*)d_in[8];
    const float* bm        = (const float*)d_in[9];
    const float* Wu        = (const float*)d_in[10];
    const float* bu        = (const float*)d_in[11];
    const float* Wp        = (const float*)d_in[12];
    const float* Wout      = (const float*)d_in[13];
    const float* bout      = (const float*)d_in[14];
    const int*   ei        = (const int*)d_in[15];
    float* out = (float*)d_out;

    // device-global scratch addresses (device-side linkage; no host API needed
    // inside the capture path beyond kernel launches)
    static float* h0 = nullptr;
    static float* h1 = nullptr;
    if (!h0) {
        cudaGetSymbolAddress((void**)&h0, g_h0buf);
        cudaGetSymbolAddress((void**)&h1, g_h1buf);
    }

    k_hbase<<<Bb, 256>>>(x, W_in, b_in);
    k_meand<<<Nn, 256>>>(positions);
    k_gfeat<<<Nn, 256>>>(Wg1, bg1, Wg2, bg2);
    k_init<<<(NNODE * Hh) / 256, 256>>>(positions);

    float* hc = h0;
    float* hn = h1;
    for (int l = 0; l < Ll; l++) {
        const float* Wml = Wm + (size_t)l * 513 * 256;
        float *Abuf, *Bbuf;
        static float* Aptr = nullptr;
        static float* Bptr = nullptr;
        if (!Aptr) {
            cudaGetSymbolAddress((void**)&Aptr, g_Abuf);
            cudaGetSymbolAddress((void**)&Bptr, g_Bbuf);
        }
        Abuf = Aptr; Bbuf = Bptr;
        k_gemm_proj<<<dim3(2, NNODE / 128), 256>>>(hc, Wml, Abuf);
        k_gemm_proj<<<dim3(2, NNODE / 128), 256>>>(hc, Wml + 256 * 256, Bbuf);
        k_zero_agg<<<(NNODE * Hh / 4) / 256, 256>>>();
        k_edge<<<Ee / 8, 256>>>(ei, Wml + 512 * 256, bm + l * 256, Wp + l * 256);
        k_posapply<<<(NNODE * 3 + 255) / 256, 256>>>();
        k_gemm_update<<<dim3(2, NNODE / 128), 256>>>(hc, Wu + (size_t)l * 512 * 256,
                                                     bu + l * 256, hn);
        float* tmp = hc; hc = hn; hn = tmp;
    }
    k_out<<<NNODE / 8, 256>>>(hc, Wout, bout, out);
}

// round 4
// speedup vs baseline: 1.8863x; 1.8863x over previous
#include <cuda_runtime.h>
#include <cuda_bf16.h>
#include <cstdint>

#define Bb    32
#define Ff    128
#define Hh    256
#define Nn    2048
#define Ll    2
#define Ee    262144
#define NNODE 65536   // B*N

// ---------------- scratch (device globals; no allocation allowed) ----------
__device__ float g_h0buf[(size_t)NNODE * Hh];
__device__ float g_h1buf[(size_t)NNODE * Hh];
__device__ float g_Abuf [(size_t)NNODE * Hh];
__device__ float g_Bbuf [(size_t)NNODE * Hh];
__device__ float g_agg  [(size_t)NNODE * Hh];
__device__ float g_pos  [(size_t)NNODE * 3];
__device__ float g_pacc [(size_t)NNODE * 3];
__device__ float g_hb   [Bb * Hh];
__device__ float g_gf   [Nn * Hh];
__device__ float g_md   [Nn];
// bf16 hi/lo activation splits (double-buffered like h0/h1)
__device__ __nv_bfloat16 g_x0h[(size_t)NNODE * Hh];
__device__ __nv_bfloat16 g_x0l[(size_t)NNODE * Hh];
__device__ __nv_bfloat16 g_x1h[(size_t)NNODE * Hh];
__device__ __nv_bfloat16 g_x1l[(size_t)NNODE * Hh];
__device__ __nv_bfloat16 g_agh[(size_t)NNODE * Hh];
__device__ __nv_bfloat16 g_agl[(size_t)NNODE * Hh];
// transposed, bf16 hi/lo split weights: Wm^T per layer: rows 0..255 = mat0,
// 256..511 = mat1, pitch 256 (k)
__device__ __nv_bfloat16 g_wm_h[(size_t)Ll * 2 * 256 * 256];
__device__ __nv_bfloat16 g_wm_l[(size_t)Ll * 2 * 256 * 256];
// Wu^T per layer [256 n][512 k]
__device__ __nv_bfloat16 g_wu_h[(size_t)Ll * 256 * 512];
__device__ __nv_bfloat16 g_wu_l[(size_t)Ll * 256 * 512];

// ---------------- helpers ----------------------------------------------------
__device__ __forceinline__ uint32_t smem_u32(const void* p) {
    uint32_t a;
    asm("{ .reg .u64 t; cvta.to.shared.u64 t, %1; cvt.u32.u64 %0, t; }" : "=r"(a) : "l"(p));
    return a;
}
__device__ __forceinline__ uint32_t swz(uint32_t o) { return o ^ ((o >> 3) & 0x70); }

__device__ __forceinline__ void cpa16(uint32_t dst, const void* src) {
    asm volatile("cp.async.cg.shared.global [%0], [%1], 16;" :: "r"(dst), "l"(src));
}
#define CPCOMMIT() asm volatile("cp.async.commit_group;" ::: "memory")
#define CPWAIT0()  asm volatile("cp.async.wait_group 0;" ::: "memory")
#define CPWAIT1()  asm volatile("cp.async.wait_group 1;" ::: "memory")

#define LDSM4(r0, r1, r2, r3, a) \
    asm volatile("ldmatrix.sync.aligned.m8n8.x4.shared.b16 {%0,%1,%2,%3}, [%4];" \
        : "=r"(r0), "=r"(r1), "=r"(r2), "=r"(r3) : "r"(a))

#define MMA16816(d, a, b) \
    asm volatile("mma.sync.aligned.m16n8k16.row.col.f32.bf16.bf16.f32 " \
        "{%0,%1,%2,%3},{%4,%5,%6,%7},{%8,%9},{%0,%1,%2,%3};" \
        : "+f"((d)[0]), "+f"((d)[1]), "+f"((d)[2]), "+f"((d)[3]) \
        : "r"((a)[0]), "r"((a)[1]), "r"((a)[2]), "r"((a)[3]), "r"((b)[0]), "r"((b)[1]))

__device__ __forceinline__ void splitv(float v, __nv_bfloat16& h, __nv_bfloat16& l) {
    h = __float2bfloat16(v);
    l = __float2bfloat16(v - __bfloat162float(h));
}

// ---------------- weight prep (transpose + bf16 hi/lo split) ---------------
__global__ void k_wmprep(const float* __restrict__ Wm) {
    int idx = blockIdx.x * 256 + threadIdx.x;           // Ll*2*65536
    int l = idx >> 17;
    int r = idx & 131071;
    int mat = r >> 16;
    int r2 = r & 65535;
    int n = r2 >> 8, k = r2 & 255;
    float v = Wm[(size_t)l * 513 * 256 + (size_t)(mat * 256 + k) * 256 + n];
    __nv_bfloat16 h, lo;
    splitv(v, h, lo);
    size_t o = ((size_t)(l * 2 + mat) * 256 + n) * 256 + k;
    g_wm_h[o] = h;
    g_wm_l[o] = lo;
}
__global__ void k_wuprep(const float* __restrict__ Wu) {
    int idx = blockIdx.x * 256 + threadIdx.x;           // Ll*131072
    int l = idx >> 17;
    int r = idx & 131071;
    int n = r >> 9, k = r & 511;
    float v = Wu[(size_t)l * 512 * 256 + (size_t)k * 256 + n];
    __nv_bfloat16 h, lo;
    splitv(v, h, lo);
    size_t o = (size_t)l * 131072 + (size_t)n * 512 + k;
    g_wu_h[o] = h;
    g_wu_l[o] = lo;
}

// ---------------- small prologue kernels -----------------------------------
__global__ void k_hbase(const float* __restrict__ x, const float* __restrict__ W_in,
                        const float* __restrict__ b_in) {
    __shared__ float xb[Ff];
    int b = blockIdx.x;
    if (threadIdx.x < Ff) xb[threadIdx.x] = x[b * Ff + threadIdx.x];
    __syncthreads();
    int j = threadIdx.x;
    float acc = b_in[j];
    #pragma unroll 4
    for (int k = 0; k < Ff; k++) acc = fmaf(xb[k], W_in[k * Hh + j], acc);
    g_hb[b * Hh + j] = acc;
}

__global__ void k_meand(const float* __restrict__ positions) {
    __shared__ float sp[Nn * 3];
    __shared__ float red[256];
    int i = blockIdx.x;
    for (int t = threadIdx.x; t < Nn * 3; t += 256) sp[t] = positions[t];
    __syncthreads();
    float px = sp[i * 3], py = sp[i * 3 + 1], pz = sp[i * 3 + 2];
    float sum = 0.f;
    for (int j = threadIdx.x; j < Nn; j += 256) {
        if (j == i) continue;
        float dx = px - sp[j * 3], dy = py - sp[j * 3 + 1], dz = pz - sp[j * 3 + 2];
        sum += sqrtf(dx * dx + dy * dy + dz * dz);
    }
    red[threadIdx.x] = sum;
    __syncthreads();
    for (int s = 128; s; s >>= 1) {
        if (threadIdx.x < s) red[threadIdx.x] += red[threadIdx.x + s];
        __syncthreads();
    }
    if (threadIdx.x == 0) g_md[i] = red[0] / (float)(Nn - 1);
}

__global__ void k_gfeat(const float* __restrict__ Wg1, const float* __restrict__ bg1,
                        const float* __restrict__ Wg2, const float* __restrict__ bg2) {
    __shared__ float t[Ff];
    int n = blockIdx.x;
    float m = g_md[n];
    if (threadIdx.x < 128) {
        int kk = threadIdx.x;
        float w = Wg1[kk] + Wg1[128 + kk] + Wg1[256 + kk];
        t[kk] = fmaxf(fmaf(m, w, bg1[kk]), 0.f);
    }
    __syncthreads();
    int j = threadIdx.x;
    float acc = bg2[j];
    #pragma unroll 4
    for (int kk = 0; kk < 128; kk++) acc = fmaf(t[kk], Wg2[kk * Hh + j], acc);
    g_gf[n * Hh + j] = acc;
}

// h init + bf16 split + pos broadcast
__global__ void k_init(const float* __restrict__ positions) {
    int i = blockIdx.x * 256 + threadIdx.x;
    int node = i >> 8, j = i & 255;
    int b = node >> 11;
    int n = node & 2047;
    float v = g_hb[b * Hh + j] + g_gf[n * Hh + j];
    g_h0buf[i] = v;
    __nv_bfloat16 h, lo;
    splitv(v, h, lo);
    g_x0h[i] = h;
    g_x0l[i] = lo;
    if (i < NNODE * 3) {
        int nd = i / 3;
        int k = i - nd * 3;
        g_pos[i] = positions[(nd & 2047) * 3 + k];
    }
}

__global__ void k_zero_agg() {
    int i = blockIdx.x * 256 + threadIdx.x;
    ((float4*)g_agg)[i] = make_float4(0.f, 0.f, 0.f, 0.f);
    if (i < NNODE * 3 / 4) ((float4*)g_pacc)[i] = make_float4(0.f, 0.f, 0.f, 0.f);
}

__global__ void k_posapply() {
    int i = blockIdx.x * 256 + threadIdx.x;
    if (i < NNODE * 3) g_pos[i] += g_pacc[i] * 0.25f;
}

// agg fp32 -> bf16 hi/lo split
__global__ void k_split_agg() {
    int i = blockIdx.x * 256 + threadIdx.x;   // NNODE*Hh
    float v = g_agg[i];
    __nv_bfloat16 h, lo;
    splitv(v, h, lo);
    g_agh[i] = h;
    g_agl[i] = lo;
}

// ---------------- HMMA GEMM (mma.sync bf16 split-precision) ----------------
// CTA tile 128(M) x 128(N), K-chunks of 64 bf16; 8 warps, each 32x64.
// SMEM stage: Ahi(16K) Alo(16K) Bhi(16K) Blo(16K) = 64K, double buffered.
// C = Ah*Bh + Ah*Bl + Al*Bh  (fp32 accum).
// mode 0 (proj, N=512): col<256 -> out0 (Abuf), else out1 (Bbuf).
// mode 1 (update):      out0 = Xres + relu(C + bias); also writes osh/osl split.
#define MM_SMEM 131072

__global__ __launch_bounds__(256) void k_mma(
    const __nv_bfloat16* __restrict__ Ah0, const __nv_bfloat16* __restrict__ Al0,
    const __nv_bfloat16* __restrict__ Ah1, const __nv_bfloat16* __restrict__ Al1,
    const __nv_bfloat16* __restrict__ Bh, const __nv_bfloat16* __restrict__ Bl,
    int bpitch, int nchunks, int mode,
    const float* __restrict__ bias, const float* __restrict__ Xres,
    float* __restrict__ out0, float* __restrict__ out1,
    __nv_bfloat16* __restrict__ osh, __nv_bfloat16* __restrict__ osl)
{
    extern __shared__ char smem[];
    uint32_t sb = smem_u32(smem);
    int tid = threadIdx.x, wid = tid >> 5, lane = tid & 31;
    int row0 = blockIdx.y * 128, n0 = blockIdx.x * 128;
    int wm = wid & 3, wn = wid >> 2;    // warp tile: rows wm*32, cols wn*64

    float acc[2][8][4];
    #pragma unroll
    for (int a = 0; a < 2; a++)
        #pragma unroll
        for (int b = 0; b < 8; b++)
            #pragma unroll
            for (int c = 0; c < 4; c++) acc[a][b][c] = 0.f;

    auto stage = [&](int c, int buf) {
        uint32_t base = sb + buf * 65536;
        #pragma unroll
        for (int i = 0; i < 16; i++) {
            int idx = i * 256 + tid;
            int mat = idx >> 10, r = idx & 1023, row = r >> 3, c16 = r & 7;
            const __nv_bfloat16* src;
            if (mat < 2) {
                const __nv_bfloat16* As = (c < 4) ? (mat ? Al0 : Ah0)
                                                  : (mat ? Al1 : Ah1);
                int ck = (c < 4) ? c : c - 4;
                src = As + (size_t)(row0 + row) * 256 + ck * 64 + c16 * 8;
            } else {
                src = ((mat == 2) ? Bh : Bl) + (size_t)(n0 + row) * bpitch + c * 64 + c16 * 8;
            }
            cpa16(base + mat * 16384 + swz(row * 128 + c16 * 16), src);
        }
        CPCOMMIT();
    };

    stage(0, 0);
    for (int c = 0; c < nchunks; c++) {
        int buf = c & 1;
        bool pf = (c + 1 < nchunks);
        if (pf) stage(c + 1, buf ^ 1);
        if (pf) CPWAIT1(); else CPWAIT0();
        __syncthreads();

        uint32_t Abase = sb + buf * 65536;
        int arow = wm * 32 + (lane & 7) + ((lane >> 3) & 1) * 8;
        int akb = ((lane >> 4) & 1) * 16;
        int brow = wn * 64 + (lane & 7) + ((lane >> 4) & 1) * 8;
        int bkb = ((lane >> 3) & 1) * 16;

        #pragma unroll
        for (int k16 = 0; k16 < 4; k16++) {
            uint32_t a_h[2][4], a_l[2][4], b_h[8][2], b_l[8][2];
            #pragma unroll
            for (int mf = 0; mf < 2; mf++) {
                uint32_t ad = Abase + swz((arow + mf * 16) * 128 + k16 * 32 + akb);
                LDSM4(a_h[mf][0], a_h[mf][1], a_h[mf][2], a_h[mf][3], ad);
                LDSM4(a_l[mf][0], a_l[mf][1], a_l[mf][2], a_l[mf][3], ad + 16384);
            }
            #pragma unroll
            for (int nf2 = 0; nf2 < 4; nf2++) {
                uint32_t bd = Abase + 32768 + swz((brow + nf2 * 16) * 128 + k16 * 32 + bkb);
                LDSM4(b_h[2 * nf2][0], b_h[2 * nf2][1],
                      b_h[2 * nf2 + 1][0], b_h[2 * nf2 + 1][1], bd);
                LDSM4(b_l[2 * nf2][0], b_l[2 * nf2][1],
                      b_l[2 * nf2 + 1][0], b_l[2 * nf2 + 1][1], bd + 16384);
            }
            #pragma unroll
            for (int mf = 0; mf < 2; mf++)
                #pragma unroll
                for (int nf = 0; nf < 8; nf++) {
                    MMA16816(acc[mf][nf], a_h[mf], b_h[nf]);
                    MMA16816(acc[mf][nf], a_h[mf], b_l[nf]);
                    MMA16816(acc[mf][nf], a_l[mf], b_h[nf]);
                }
        }
        __syncthreads();
    }

    // epilogue
    int r_base = row0 + wm * 32 + (lane >> 2);
    int c_base = n0 + wn * 64 + 2 * (lane & 3);
    if (mode == 0) {
        #pragma unroll
        for (int mf = 0; mf < 2; mf++)
            #pragma unroll
            for (int nf = 0; nf < 8; nf++) {
                int r = r_base + mf * 16;
                int col = c_base + nf * 8;
                float* ob = (col < 256) ? out0 : out1;
                int cc = col & 255;
                *(float2*)(ob + (size_t)r * 256 + cc) =
                    make_float2(acc[mf][nf][0], acc[mf][nf][1]);
                *(float2*)(ob + (size_t)(r + 8) * 256 + cc) =
                    make_float2(acc[mf][nf][2], acc[mf][nf][3]);
            }
    } else {
        #pragma unroll
        for (int mf = 0; mf < 2; mf++)
            #pragma unroll
            for (int nf = 0; nf < 8; nf++) {
                int col = c_base + nf * 8;
                float b0 = bias[col], b1 = bias[col + 1];
                #pragma unroll
                for (int hr = 0; hr < 2; hr++) {
                    int r = r_base + mf * 16 + hr * 8;
                    size_t off = (size_t)r * 256 + col;
                    float2 xv = *(const float2*)(Xres + off);
                    float o0 = xv.x + fmaxf(acc[mf][nf][hr * 2]     + b0, 0.f);
                    float o1 = xv.y + fmaxf(acc[mf][nf][hr * 2 + 1] + b1, 0.f);
                    *(float2*)(out0 + off) = make_float2(o0, o1);
                    __nv_bfloat16 h0, l0, h1, l1;
                    splitv(o0, h0, l0);
                    splitv(o1, h1, l1);
                    uint32_t ph = (uint32_t)__bfloat16_as_ushort(h0)
                                | ((uint32_t)__bfloat16_as_ushort(h1) << 16);
                    uint32_t pl = (uint32_t)__bfloat16_as_ushort(l0)
                                | ((uint32_t)__bfloat16_as_ushort(l1) << 16);
                    *(uint32_t*)(osh + off) = ph;
                    *(uint32_t*)(osl + off) = pl;
                }
            }
    }
}

// ---------------- edge kernel: 1 warp / edge --------------------------------
__global__ __launch_bounds__(256) void k_edge(const int* __restrict__ ei,
                                              const float* __restrict__ wd,
                                              const float* __restrict__ bmv,
                                              const float* __restrict__ wp) {
    int e = (blockIdx.x << 3) + (threadIdx.x >> 5);
    int lane = threadIdx.x & 31;
    int s = __ldg(ei + e);
    int t = __ldg(ei + Ee + e);

    const float* pos = g_pos;
    float psx = pos[s * 3], psy = pos[s * 3 + 1], psz = pos[s * 3 + 2];
    float ptx = pos[t * 3], pty = pos[t * 3 + 1], ptz = pos[t * 3 + 2];
    float dx = psx - ptx, dy = psy - pty, dz = psz - ptz;
    float d = sqrtf(dx * dx + dy * dy + dz * dz + 1e-12f);

    int j0 = lane << 3;
    const float4* A4 = (const float4*)(g_Abuf + ((size_t)s << 8) + j0);
    const float4* B4 = (const float4*)(g_Bbuf + ((size_t)t << 8) + j0);
    float4 a0 = A4[0], a1 = A4[1];
    float4 b0 = B4[0], b1 = B4[1];
    float4 w0 = *(const float4*)(wd + j0),  w1 = *(const float4*)(wd + j0 + 4);
    float4 c0 = *(const float4*)(bmv + j0), c1 = *(const float4*)(bmv + j0 + 4);
    float4 p0 = *(const float4*)(wp + j0),  p1 = *(const float4*)(wp + j0 + 4);

    float4 m0, m1;
    m0.x = fmaxf(fmaf(d, w0.x, a0.x + b0.x + c0.x), 0.f);
    m0.y = fmaxf(fmaf(d, w0.y, a0.y + b0.y + c0.y), 0.f);
    m0.z = fmaxf(fmaf(d, w0.z, a0.z + b0.z + c0.z), 0.f);
    m0.w = fmaxf(fmaf(d, w0.w, a0.w + b0.w + c0.w), 0.f);
    m1.x = fmaxf(fmaf(d, w1.x, a1.x + b1.x + c1.x), 0.f);
    m1.y = fmaxf(fmaf(d, w1.y, a1.y + b1.y + c1.y), 0.f);
    m1.z = fmaxf(fmaf(d, w1.z, a1.z + b1.z + c1.z), 0.f);
    m1.w = fmaxf(fmaf(d, w1.w, a1.w + b1.w + c1.w), 0.f);

    float cf = m0.x * p0.x + m0.y * p0.y + m0.z * p0.z + m0.w * p0.w
             + m1.x * p1.x + m1.y * p1.y + m1.z * p1.z + m1.w * p1.w;

    float* ag = g_agg + ((size_t)t << 8) + j0;
    asm volatile("red.global.add.v4.f32 [%0], {%1,%2,%3,%4};"
                 :: "l"(ag), "f"(m0.x), "f"(m0.y), "f"(m0.z), "f"(m0.w) : "memory");
    asm volatile("red.global.add.v4.f32 [%0], {%1,%2,%3,%4};"
                 :: "l"(ag + 4), "f"(m1.x), "f"(m1.y), "f"(m1.z), "f"(m1.w) : "memory");

    #pragma unroll
    for (int off = 16; off; off >>= 1) cf += __shfl_xor_sync(0xffffffffu, cf, off);

    if (lane < 3) {
        float pd = (lane == 0) ? (ptx - psx) : (lane == 1) ? (pty - psy) : (ptz - psz);
        atomicAdd(g_pacc + (size_t)t * 3 + lane, pd * cf);
    }
}

// ---------------- output GEMV ----------------------------------------------
__global__ void k_out(const float* __restrict__ h, const float* __restrict__ Wout,
                      const float* __restrict__ bout, float* __restrict__ out) {
    int warp = (blockIdx.x * blockDim.x + threadIdx.x) >> 5;
    int lane = threadIdx.x & 31;
    if (warp >= NNODE) return;
    const float4* h4 = (const float4*)(h + (size_t)warp * 256);
    const float4* w4 = (const float4*)Wout;
    float acc = 0.f;
    float4 a = h4[lane * 2], b = w4[lane * 2];
    acc += a.x * b.x + a.y * b.y + a.z * b.z + a.w * b.w;
    a = h4[lane * 2 + 1]; b = w4[lane * 2 + 1];
    acc += a.x * b.x + a.y * b.y + a.z * b.z + a.w * b.w;
    #pragma unroll
    for (int off = 16; off; off >>= 1) acc += __shfl_xor_sync(0xffffffffu, acc, off);
    if (lane == 0) out[warp] = acc + bout[0];
}

// ---------------- launch ----------------------------------------------------
extern "C" void kernel_launch(void* const* d_in, const int* in_sizes, int n_in,
                              void* d_out, int out_size) {
    const float* x         = (const float*)d_in[0];
    const float* positions = (const float*)d_in[1];
    const float* W_in      = (const float*)d_in[2];
    const float* b_in      = (const float*)d_in[3];
    const float* Wg1       = (const float*)d_in[4];
    const float* bg1       = (const float*)d_in[5];
    const float* Wg2       = (const float*)d_in[6];
    const float* bg2       = (const float*)d_in[7];
    const float* Wm        = (const float*)d_in[8];
    const float* bm        = (const float*)d_in[9];
    const float* Wu        = (const float*)d_in[10];
    const float* bu        = (const float*)d_in[11];
    const float* Wp        = (const float*)d_in[12];
    const float* Wout      = (const float*)d_in[13];
    const float* bout      = (const float*)d_in[14];
    const int*   ei        = (const int*)d_in[15];
    float* out = (float*)d_out;

    static float* h0 = nullptr;
    static float* h1 = nullptr;
    static float* abuf = nullptr;
    static float* bbuf = nullptr;
    static __nv_bfloat16 *x0h, *x0l, *x1h, *x1l, *agh, *agl, *wmh, *wml, *wuh, *wul;
    if (!h0) {
        cudaGetSymbolAddress((void**)&h0,   g_h0buf);
        cudaGetSymbolAddress((void**)&h1,   g_h1buf);
        cudaGetSymbolAddress((void**)&abuf, g_Abuf);
        cudaGetSymbolAddress((void**)&bbuf, g_Bbuf);
        cudaGetSymbolAddress((void**)&x0h,  g_x0h);
        cudaGetSymbolAddress((void**)&x0l,  g_x0l);
        cudaGetSymbolAddress((void**)&x1h,  g_x1h);
        cudaGetSymbolAddress((void**)&x1l,  g_x1l);
        cudaGetSymbolAddress((void**)&agh,  g_agh);
        cudaGetSymbolAddress((void**)&agl,  g_agl);
        cudaGetSymbolAddress((void**)&wmh,  g_wm_h);
        cudaGetSymbolAddress((void**)&wml,  g_wm_l);
        cudaGetSymbolAddress((void**)&wuh,  g_wu_h);
        cudaGetSymbolAddress((void**)&wul,  g_wu_l);
        cudaFuncSetAttribute(k_mma, cudaFuncAttributeMaxDynamicSharedMemorySize, MM_SMEM);
    }

    k_wmprep<<<(Ll * 2 * 65536) / 256, 256>>>(Wm);
    k_wuprep<<<(Ll * 131072) / 256, 256>>>(Wu);
    k_hbase<<<Bb, 256>>>(x, W_in, b_in);
    k_meand<<<Nn, 256>>>(positions);
    k_gfeat<<<Nn, 256>>>(Wg1, bg1, Wg2, bg2);
    k_init<<<(NNODE * Hh) / 256, 256>>>(positions);

    float* hc = h0;
    float* hn = h1;
    __nv_bfloat16 *sch = x0h, *scl = x0l, *snh = x1h, *snl = x1l;
    for (int l = 0; l < Ll; l++) {
        const float* Wml = Wm + (size_t)l * 513 * 256;
        // proj: C[M,512] = h @ [Wm1 | Wm2]
        k_mma<<<dim3(4, NNODE / 128), 256, MM_SMEM>>>(
            sch, scl, sch, scl,
            wmh + (size_t)l * 2 * 65536, wml + (size_t)l * 2 * 65536,
            256, 4, 0, nullptr, nullptr, abuf, bbuf, nullptr, nullptr);
        k_zero_agg<<<(NNODE * Hh / 4) / 256, 256>>>();
        k_edge<<<Ee / 8, 256>>>(ei, Wml + 512 * 256, bm + l * 256, Wp + l * 256);
        k_posapply<<<(NNODE * 3 + 255) / 256, 256>>>();
        k_split_agg<<<(NNODE * Hh) / 256, 256>>>();
        // update: Hout = h + relu(concat(h, agg) @ Wu + bu)
        k_mma<<<dim3(2, NNODE / 128), 256, MM_SMEM>>>(
            sch, scl, agh, agl,
            wuh + (size_t)l * 131072, wul + (size_t)l * 131072,
            512, 8, 1, bu + l * 256, hc, hn, nullptr, snh, snl);
        float* tmp = hc; hc = hn; hn = tmp;
        __nv_bfloat16* tb;
        tb = sch; sch = snh; snh = tb;
        tb = scl; scl = snl; snl = tb;
    }
    k_out<<<NNODE / 8, 256>>>(hc, Wout, bout, out);
}

// round 6
// speedup vs baseline: 1.9152x; 1.0154x over previous
#include <cuda_runtime.h>
#include <cuda_bf16.h>
#include <cstdint>

#define Bb    32
#define Ff    128
#define Hh    256
#define Nn    2048
#define Ll    2
#define Ee    262144
#define NNODE 65536   // B*N

// ---------------- scratch (device globals; no allocation allowed) ----------
__device__ float g_h0buf[(size_t)NNODE * Hh];
__device__ float g_h1buf[(size_t)NNODE * Hh];
__device__ float g_Abuf [(size_t)NNODE * Hh];
__device__ float g_Bbuf [(size_t)NNODE * Hh];
__device__ float g_agg  [(size_t)NNODE * Hh];
__device__ float g_pos  [(size_t)NNODE * 3];
__device__ float g_pacc [(size_t)NNODE * 3];
__device__ float g_hb   [Bb * Hh];
__device__ float g_gf   [Nn * Hh];
__device__ float g_md   [Nn];
// transposed, bf16 hi/lo split weights: Wm^T per layer (rows 0..255 = mat0,
// 256..511 = mat1), k-pitch 256
__device__ __nv_bfloat16 g_wm_h[(size_t)Ll * 2 * 256 * 256];
__device__ __nv_bfloat16 g_wm_l[(size_t)Ll * 2 * 256 * 256];
// Wu^T per layer [256 n][512 k]
__device__ __nv_bfloat16 g_wu_h[(size_t)Ll * 256 * 512];
__device__ __nv_bfloat16 g_wu_l[(size_t)Ll * 256 * 512];

// ---------------- helpers ----------------------------------------------------
__device__ __forceinline__ uint32_t smem_u32(const void* p) {
    uint32_t a;
    asm("{ .reg .u64 t; cvta.to.shared.u64 t, %1; cvt.u32.u64 %0, t; }" : "=r"(a) : "l"(p));
    return a;
}
__device__ __forceinline__ uint32_t swz(uint32_t o) { return o ^ ((o >> 3) & 0x70); }

__device__ __forceinline__ void cpa16(uint32_t dst, const void* src) {
    asm volatile("cp.async.cg.shared.global [%0], [%1], 16;" :: "r"(dst), "l"(src));
}
#define CPCOMMIT() asm volatile("cp.async.commit_group;" ::: "memory")
#define CPWAIT0()  asm volatile("cp.async.wait_group 0;" ::: "memory")
#define CPWAIT1()  asm volatile("cp.async.wait_group 1;" ::: "memory")

#define LDSM4(r0, r1, r2, r3, a) \
    asm volatile("ldmatrix.sync.aligned.m8n8.x4.shared.b16 {%0,%1,%2,%3}, [%4];" \
        : "=r"(r0), "=r"(r1), "=r"(r2), "=r"(r3) : "r"(a))

#define MMA16816(d, a, b) \
    asm volatile("mma.sync.aligned.m16n8k16.row.col.f32.bf16.bf16.f32 " \
        "{%0,%1,%2,%3},{%4,%5,%6,%7},{%8,%9},{%0,%1,%2,%3};" \
        : "+f"((d)[0]), "+f"((d)[1]), "+f"((d)[2]), "+f"((d)[3]) \
        : "r"((a)[0]), "r"((a)[1]), "r"((a)[2]), "r"((a)[3]), "r"((b)[0]), "r"((b)[1]))

__device__ __forceinline__ void splitv(float v, __nv_bfloat16& h, __nv_bfloat16& l) {
    h = __float2bfloat16(v);
    l = __float2bfloat16(v - __bfloat162float(h));
}
// split fp32 pair -> packed (hi bf16x2, lo bf16x2)
__device__ __forceinline__ void split2(float a, float b, uint32_t& hi, uint32_t& lo) {
    __nv_bfloat16 ha, la, hb, lb;
    splitv(a, ha, la);
    splitv(b, hb, lb);
    hi = (uint32_t)__bfloat16_as_ushort(ha) | ((uint32_t)__bfloat16_as_ushort(hb) << 16);
    lo = (uint32_t)__bfloat16_as_ushort(la) | ((uint32_t)__bfloat16_as_ushort(lb) << 16);
}

// ---------------- weight prep (transpose + bf16 hi/lo split) ---------------
__global__ void k_wmprep(const float* __restrict__ Wm) {
    int idx = blockIdx.x * 256 + threadIdx.x;           // Ll*2*65536
    int l = idx >> 17;
    int r = idx & 131071;
    int mat = r >> 16;
    int r2 = r & 65535;
    int n = r2 >> 8, k = r2 & 255;
    float v = Wm[(size_t)l * 513 * 256 + (size_t)(mat * 256 + k) * 256 + n];
    __nv_bfloat16 h, lo;
    splitv(v, h, lo);
    size_t o = ((size_t)(l * 2 + mat) * 256 + n) * 256 + k;
    g_wm_h[o] = h;
    g_wm_l[o] = lo;
}
__global__ void k_wuprep(const float* __restrict__ Wu) {
    int idx = blockIdx.x * 256 + threadIdx.x;           // Ll*131072
    int l = idx >> 17;
    int r = idx & 131071;
    int n = r >> 9, k = r & 511;
    float v = Wu[(size_t)l * 512 * 256 + (size_t)k * 256 + n];
    __nv_bfloat16 h, lo;
    splitv(v, h, lo);
    size_t o = (size_t)l * 131072 + (size_t)n * 512 + k;
    g_wu_h[o] = h;
    g_wu_l[o] = lo;
}

// ---------------- small prologue kernels -----------------------------------
__global__ void k_hbase(const float* __restrict__ x, const float* __restrict__ W_in,
                        const float* __restrict__ b_in) {
    __shared__ float xb[Ff];
    int b = blockIdx.x;
    if (threadIdx.x < Ff) xb[threadIdx.x] = x[b * Ff + threadIdx.x];
    __syncthreads();
    int j = threadIdx.x;
    float acc = b_in[j];
    #pragma unroll 4
    for (int k = 0; k < Ff; k++) acc = fmaf(xb[k], W_in[k * Hh + j], acc);
    g_hb[b * Hh + j] = acc;
}

__global__ void k_meand(const float* __restrict__ positions) {
    __shared__ float sp[Nn * 3];
    __shared__ float red[256];
    int i = blockIdx.x;
    for (int t = threadIdx.x; t < Nn * 3; t += 256) sp[t] = positions[t];
    __syncthreads();
    float px = sp[i * 3], py = sp[i * 3 + 1], pz = sp[i * 3 + 2];
    float sum = 0.f;
    for (int j = threadIdx.x; j < Nn; j += 256) {
        if (j == i) continue;
        float dx = px - sp[j * 3], dy = py - sp[j * 3 + 1], dz = pz - sp[j * 3 + 2];
        sum += sqrtf(dx * dx + dy * dy + dz * dz);
    }
    red[threadIdx.x] = sum;
    __syncthreads();
    for (int s = 128; s; s >>= 1) {
        if (threadIdx.x < s) red[threadIdx.x] += red[threadIdx.x + s];
        __syncthreads();
    }
    if (threadIdx.x == 0) g_md[i] = red[0] / (float)(Nn - 1);
}

__global__ void k_gfeat(const float* __restrict__ Wg1, const float* __restrict__ bg1,
                        const float* __restrict__ Wg2, const float* __restrict__ bg2) {
    __shared__ float t[Ff];
    int n = blockIdx.x;
    float m = g_md[n];
    if (threadIdx.x < 128) {
        int kk = threadIdx.x;
        float w = Wg1[kk] + Wg1[128 + kk] + Wg1[256 + kk];
        t[kk] = fmaxf(fmaf(m, w, bg1[kk]), 0.f);
    }
    __syncthreads();
    int j = threadIdx.x;
    float acc = bg2[j];
    #pragma unroll 4
    for (int kk = 0; kk < 128; kk++) acc = fmaf(t[kk], Wg2[kk * Hh + j], acc);
    g_gf[n * Hh + j] = acc;
}

__global__ void k_init(const float* __restrict__ positions) {
    int i = blockIdx.x * 256 + threadIdx.x;
    int node = i >> 8, j = i & 255;
    int b = node >> 11;
    int n = node & 2047;
    g_h0buf[i] = g_hb[b * Hh + j] + g_gf[n * Hh + j];
    if (i < NNODE * 3) {
        int nd = i / 3;
        int k = i - nd * 3;
        g_pos[i] = positions[(nd & 2047) * 3 + k];
    }
}

__global__ void k_posapply() {
    int i = blockIdx.x * 256 + threadIdx.x;
    if (i < NNODE * 3) g_pos[i] += g_pacc[i] * 0.25f;
}

// ---------------- HMMA GEMM (mma.sync bf16 split-precision) ----------------
// CTA tile 128(M) x 128(N); K-chunks of 64; 8 warps, 32x64 each.
// A operand: fp32 source, split hi/lo ON THE FLY (LDG early, deferred STS).
//   chunks c < 4 read A0, chunks >= 4 read A1 (update GEMM K=512).
// B operand: pre-split bf16 weights via cp.async, k-pitch bpitch.
// C = Ah*Bh + Ah*Bl + Al*Bh (fp32 accum).
// mode 0 (proj): col<256 -> g_Abuf else g_Bbuf; blockIdx.x==0 CTAs also zero
//   agg/pacc rows; if zflags bit1, init out[row] = bout[0].
// mode 1 (update): out0 = Xres + relu(C + bias); if wantout, fused GEMV
//   partials atomicAdd'ed into out (pre-initialized to bout).
#define MM_SMEM 131072

__global__ __launch_bounds__(256) void k_mma(
    const float* __restrict__ A0, const float* __restrict__ A1,
    const __nv_bfloat16* __restrict__ Bh, const __nv_bfloat16* __restrict__ Bl,
    int bpitch, int nchunks, int mode,
    const float* __restrict__ bias, const float* __restrict__ Xres,
    float* __restrict__ out0, float* __restrict__ out1,
    int zflags,                      // bit0: zero agg/pacc (proj); bit1: init out
    const float* __restrict__ Wout, const float* __restrict__ bout,
    float* __restrict__ outv, int wantout)
{
    extern __shared__ char smem[];
    uint32_t sb = smem_u32(smem);
    int tid = threadIdx.x, wid = tid >> 5, lane = tid & 31;
    int row0 = blockIdx.y * 128, n0 = blockIdx.x * 128;
    int wm = wid & 3, wn = wid >> 2;

    float acc[2][8][4];
    #pragma unroll
    for (int a = 0; a < 2; a++)
        #pragma unroll
        for (int b = 0; b < 8; b++)
            #pragma unroll
            for (int c = 0; c < 4; c++) acc[a][b][c] = 0.f;

    float4 areg[8];

    auto stage_load = [&](int c) {
        const float* As = (c < 4) ? A0 : A1;
        int cb = (c & 3) * 64;
        #pragma unroll
        for (int i = 0; i < 4; i++) {
            int g = i * 256 + tid;
            int row = g >> 3, c8 = g & 7;
            const float* src = As + (size_t)(row0 + row) * 256 + cb + c8 * 8;
            areg[i * 2]     = *(const float4*)src;
            areg[i * 2 + 1] = *(const float4*)(src + 4);
        }
    };
    auto stage_store = [&](int buf) {
        #pragma unroll
        for (int i = 0; i < 4; i++) {
            int g = i * 256 + tid;
            int row = g >> 3, c8 = g & 7;
            float4 va = areg[i * 2], vb = areg[i * 2 + 1];
            uint4 hi, lo;
            split2(va.x, va.y, hi.x, lo.x);
            split2(va.z, va.w, hi.y, lo.y);
            split2(vb.x, vb.y, hi.z, lo.z);
            split2(vb.z, vb.w, hi.w, lo.w);
            uint32_t off = swz(row * 128 + c8 * 16);
            *(uint4*)(smem + buf * 65536 + off)         = hi;
            *(uint4*)(smem + buf * 65536 + 16384 + off) = lo;
        }
    };
    auto stage_b = [&](int c, int buf) {
        uint32_t base = sb + buf * 65536 + 32768;
        #pragma unroll
        for (int i = 0; i < 8; i++) {
            int g = i * 256 + tid;
            int sp = g >> 10, r = g & 1023;
            int row = r >> 3, c8 = r & 7;
            const __nv_bfloat16* src = (sp ? Bl : Bh)
                + (size_t)(n0 + row) * bpitch + c * 64 + c8 * 8;
            cpa16(base + sp * 16384 + swz(row * 128 + c8 * 16), src);
        }
        CPCOMMIT();
    };

    stage_load(0);
    stage_b(0, 0);
    stage_store(0);

    for (int c = 0; c < nchunks; c++) {
        int buf = c & 1;
        bool pf = (c + 1 < nchunks);
        if (pf) {
            stage_load(c + 1);
            stage_b(c + 1, buf ^ 1);
        }
        if (pf) CPWAIT1(); else CPWAIT0();
        __syncthreads();

        uint32_t Abase = sb + buf * 65536;
        int arow = wm * 32 + (lane & 7) + ((lane >> 3) & 1) * 8;
        int akb = ((lane >> 4) & 1) * 16;
        int brow = wn * 64 + (lane & 7) + ((lane >> 4) & 1) * 8;
        int bkb = ((lane >> 3) & 1) * 16;

        #pragma unroll
        for (int k16 = 0; k16 < 4; k16++) {
            uint32_t a_h[2][4], a_l[2][4], b_h[8][2], b_l[8][2];
            #pragma unroll
            for (int mf = 0; mf < 2; mf++) {
                uint32_t ad = Abase + swz((arow + mf * 16) * 128 + k16 * 32 + akb);
                LDSM4(a_h[mf][0], a_h[mf][1], a_h[mf][2], a_h[mf][3], ad);
                LDSM4(a_l[mf][0], a_l[mf][1], a_l[mf][2], a_l[mf][3], ad + 16384);
            }
            #pragma unroll
            for (int nf2 = 0; nf2 < 4; nf2++) {
                uint32_t bd = Abase + 32768 + swz((brow + nf2 * 16) * 128 + k16 * 32 + bkb);
                LDSM4(b_h[2 * nf2][0], b_h[2 * nf2][1],
                      b_h[2 * nf2 + 1][0], b_h[2 * nf2 + 1][1], bd);
                LDSM4(b_l[2 * nf2][0], b_l[2 * nf2][1],
                      b_l[2 * nf2 + 1][0], b_l[2 * nf2 + 1][1], bd + 16384);
            }
            #pragma unroll
            for (int mf = 0; mf < 2; mf++)
                #pragma unroll
                for (int nf = 0; nf < 8; nf++) {
                    MMA16816(acc[mf][nf], a_h[mf], b_h[nf]);
                    MMA16816(acc[mf][nf], a_h[mf], b_l[nf]);
                    MMA16816(acc[mf][nf], a_l[mf], b_h[nf]);
                }
        }
        if (pf) stage_store(buf ^ 1);
        __syncthreads();
    }

    // ---------------- epilogue ----------------
    int r_base = row0 + wm * 32 + (lane >> 2);
    int c_base = n0 + wn * 64 + 2 * (lane & 3);
    if (mode == 0) {
        #pragma unroll
        for (int mf = 0; mf < 2; mf++)
            #pragma unroll
            for (int nf = 0; nf < 8; nf++) {
                int r = r_base + mf * 16;
                int col = c_base + nf * 8;
                float* ob = (col < 256) ? out0 : out1;
                int cc = col & 255;
                *(float2*)(ob + (size_t)r * 256 + cc) =
                    make_float2(acc[mf][nf][0], acc[mf][nf][1]);
                *(float2*)(ob + (size_t)(r + 8) * 256 + cc) =
                    make_float2(acc[mf][nf][2], acc[mf][nf][3]);
            }
        if (blockIdx.x == 0) {
            if (zflags & 1) {
                // zero 128 rows x 256 floats of agg = 8192 float4 (32 iters x 256 thr)
                float4* az = (float4*)(g_agg + (size_t)row0 * 256);
                #pragma unroll
                for (int i = 0; i < 32; i++)
                    az[i * 256 + tid] = make_float4(0.f, 0.f, 0.f, 0.f);
                if (tid < 96)
                    ((float4*)(g_pacc + (size_t)row0 * 3))[tid] =
                        make_float4(0.f, 0.f, 0.f, 0.f);
            }
            if ((zflags & 2) && tid < 128) outv[row0 + tid] = bout[0];
        }
    } else {
        float wpart[2][2] = {{0.f, 0.f}, {0.f, 0.f}};
        #pragma unroll
        for (int mf = 0; mf < 2; mf++)
            #pragma unroll
            for (int nf = 0; nf < 8; nf++) {
                int col = c_base + nf * 8;
                float b0 = bias[col], b1 = bias[col + 1];
                float w0 = 0.f, w1 = 0.f;
                if (wantout) { w0 = Wout[col]; w1 = Wout[col + 1]; }
                #pragma unroll
                for (int hr = 0; hr < 2; hr++) {
                    int r = r_base + mf * 16 + hr * 8;
                    size_t off = (size_t)r * 256 + col;
                    float2 xv = *(const float2*)(Xres + off);
                    float o0 = xv.x + fmaxf(acc[mf][nf][hr * 2]     + b0, 0.f);
                    float o1 = xv.y + fmaxf(acc[mf][nf][hr * 2 + 1] + b1, 0.f);
                    *(float2*)(out0 + off) = make_float2(o0, o1);
                    wpart[mf][hr] += o0 * w0 + o1 * w1;
                }
            }
        if (wantout) {
            #pragma unroll
            for (int mf = 0; mf < 2; mf++)
                #pragma unroll
                for (int hr = 0; hr < 2; hr++) {
                    float v = wpart[mf][hr];
                    v += __shfl_xor_sync(0xffffffffu, v, 1);
                    v += __shfl_xor_sync(0xffffffffu, v, 2);
                    if ((lane & 3) == 0)
                        atomicAdd(outv + r_base + mf * 16 + hr * 8, v);
                }
        }
    }
}

// ---------------- edge kernel: 1 warp / edge --------------------------------
__global__ __launch_bounds__(256) void k_edge(const int* __restrict__ ei,
                                              const float* __restrict__ wd,
                                              const float* __restrict__ bmv,
                                              const float* __restrict__ wp) {
    int e = (blockIdx.x << 3) + (threadIdx.x >> 5);
    int lane = threadIdx.x & 31;
    int s = __ldg(ei + e);
    int t = __ldg(ei + Ee + e);

    const float* pos = g_pos;
    float psx = pos[s * 3], psy = pos[s * 3 + 1], psz = pos[s * 3 + 2];
    float ptx = pos[t * 3], pty = pos[t * 3 + 1], ptz = pos[t * 3 + 2];
    float dx = psx - ptx, dy = psy - pty, dz = psz - ptz;
    float d = sqrtf(dx * dx + dy * dy + dz * dz + 1e-12f);

    int j0 = lane << 3;
    const float4* A4 = (const float4*)(g_Abuf + ((size_t)s << 8) + j0);
    const float4* B4 = (const float4*)(g_Bbuf + ((size_t)t << 8) + j0);
    float4 a0 = A4[0], a1 = A4[1];
    float4 b0 = B4[0], b1 = B4[1];
    float4 w0 = *(const float4*)(wd + j0),  w1 = *(const float4*)(wd + j0 + 4);
    float4 c0 = *(const float4*)(bmv + j0), c1 = *(const float4*)(bmv + j0 + 4);
    float4 p0 = *(const float4*)(wp + j0),  p1 = *(const float4*)(wp + j0 + 4);

    float4 m0, m1;
    m0.x = fmaxf(fmaf(d, w0.x, a0.x + b0.x + c0.x), 0.f);
    m0.y = fmaxf(fmaf(d, w0.y, a0.y + b0.y + c0.y), 0.f);
    m0.z = fmaxf(fmaf(d, w0.z, a0.z + b0.z + c0.z), 0.f);
    m0.w = fmaxf(fmaf(d, w0.w, a0.w + b0.w + c0.w), 0.f);
    m1.x = fmaxf(fmaf(d, w1.x, a1.x + b1.x + c1.x), 0.f);
    m1.y = fmaxf(fmaf(d, w1.y, a1.y + b1.y + c1.y), 0.f);
    m1.z = fmaxf(fmaf(d, w1.z, a1.z + b1.z + c1.z), 0.f);
    m1.w = fmaxf(fmaf(d, w1.w, a1.w + b1.w + c1.w), 0.f);

    float cf = m0.x * p0.x + m0.y * p0.y + m0.z * p0.z + m0.w * p0.w
             + m1.x * p1.x + m1.y * p1.y + m1.z * p1.z + m1.w * p1.w;

    float* ag = g_agg + ((size_t)t << 8) + j0;
    asm volatile("red.global.add.v4.f32 [%0], {%1,%2,%3,%4};"
                 :: "l"(ag), "f"(m0.x), "f"(m0.y), "f"(m0.z), "f"(m0.w) : "memory");
    asm volatile("red.global.add.v4.f32 [%0], {%1,%2,%3,%4};"
                 :: "l"(ag + 4), "f"(m1.x), "f"(m1.y), "f"(m1.z), "f"(m1.w) : "memory");

    #pragma unroll
    for (int off = 16; off; off >>= 1) cf += __shfl_xor_sync(0xffffffffu, cf, off);

    if (lane < 3) {
        float pd = (lane == 0) ? (ptx - psx) : (lane == 1) ? (pty - psy) : (ptz - psz);
        atomicAdd(g_pacc + (size_t)t * 3 + lane, pd * cf);
    }
}

// ---------------- launch ----------------------------------------------------
extern "C" void kernel_launch(void* const* d_in, const int* in_sizes, int n_in,
                              void* d_out, int out_size) {
    const float* x         = (const float*)d_in[0];
    const float* positions = (const float*)d_in[1];
    const float* W_in      = (const float*)d_in[2];
    const float* b_in      = (const float*)d_in[3];
    const float* Wg1       = (const float*)d_in[4];
    const float* bg1       = (const float*)d_in[5];
    const float* Wg2       = (const float*)d_in[6];
    const float* bg2       = (const float*)d_in[7];
    const float* Wm        = (const float*)d_in[8];
    const float* bm        = (const float*)d_in[9];
    const float* Wu        = (const float*)d_in[10];
    const float* bu        = (const float*)d_in[11];
    const float* Wp        = (const float*)d_in[12];
    const float* Wout      = (const float*)d_in[13];
    const float* bout      = (const float*)d_in[14];
    const int*   ei        = (const int*)d_in[15];
    float* out = (float*)d_out;

    static float* h0 = nullptr;
    static float* h1 = nullptr;
    static float* abuf = nullptr;
    static float* bbuf = nullptr;
    static float* aggp = nullptr;
    static __nv_bfloat16 *wmh, *wml, *wuh, *wul;
    if (!h0) {
        cudaGetSymbolAddress((void**)&h0,   g_h0buf);
        cudaGetSymbolAddress((void**)&h1,   g_h1buf);
        cudaGetSymbolAddress((void**)&abuf, g_Abuf);
        cudaGetSymbolAddress((void**)&bbuf, g_Bbuf);
        cudaGetSymbolAddress((void**)&aggp, g_agg);
        cudaGetSymbolAddress((void**)&wmh,  g_wm_h);
        cudaGetSymbolAddress((void**)&wml,  g_wm_l);
        cudaGetSymbolAddress((void**)&wuh,  g_wu_h);
        cudaGetSymbolAddress((void**)&wul,  g_wu_l);
        cudaFuncSetAttribute(k_mma, cudaFuncAttributeMaxDynamicSharedMemorySize, MM_SMEM);
    }

    k_wmprep<<<(Ll * 2 * 65536) / 256, 256>>>(Wm);
    k_wuprep<<<(Ll * 131072) / 256, 256>>>(Wu);
    k_hbase<<<Bb, 256>>>(x, W_in, b_in);
    k_meand<<<Nn, 256>>>(positions);
    k_gfeat<<<Nn, 256>>>(Wg1, bg1, Wg2, bg2);
    k_init<<<(NNODE * Hh) / 256, 256>>>(positions);

    float* hc = h0;
    float* hn = h1;
    for (int l = 0; l < Ll; l++) {
        const float* Wml = Wm + (size_t)l * 513 * 256;
        int zf = 1 | ((l == Ll - 1) ? 2 : 0);
        // proj: [Abuf|Bbuf] = h @ [Wm1|Wm2]; fused agg/pacc zero (+out init on last layer)
        k_mma<<<dim3(4, NNODE / 128), 256, MM_SMEM>>>(
            hc, nullptr,
            wmh + (size_t)l * 2 * 65536, wml + (size_t)l * 2 * 65536,
            256, 4, 0, nullptr, nullptr, abuf, bbuf,
            zf, nullptr, bout, out, 0);
        k_edge<<<Ee / 8, 256>>>(ei, Wml + 512 * 256, bm + l * 256, Wp + l * 256);
        k_posapply<<<(NNODE * 3 + 255) / 256, 256>>>();
        // update: hn = h + relu(concat(h, agg) @ Wu + bu); fused output GEMV on last layer
        k_mma<<<dim3(2, NNODE / 128), 256, MM_SMEM>>>(
            hc, aggp,
            wuh + (size_t)l * 131072, wul + (size_t)l * 131072,
            512, 8, 1, bu + l * 256, hc, hn, nullptr,
            0, Wout, bout, out, (l == Ll - 1) ? 1 : 0);
        float* tmp = hc; hc = hn; hn = tmp;
    }
}

// round 7
// speedup vs baseline: 1.9752x; 1.0313x over previous
#include <cuda_runtime.h>
#include <cuda_bf16.h>
#include <cstdint>

#define Bb    32
#define Ff    128
#define Hh    256
#define Nn    2048
#define Ll    2
#define Ee    262144
#define NNODE 65536   // B*N

// ---------------- scratch (device globals; no allocation allowed) ----------
__device__ float g_h0buf[(size_t)NNODE * Hh];
__device__ float g_h1buf[(size_t)NNODE * Hh];
__device__ float g_Abuf [(size_t)NNODE * Hh];
__device__ float g_Bbuf [(size_t)NNODE * Hh];
__device__ float g_agg  [(size_t)NNODE * Hh];
__device__ float g_pos  [(size_t)NNODE * 3];
__device__ float g_pacc [(size_t)NNODE * 3];
__device__ float g_hb   [Bb * Hh];
__device__ float g_gf   [Nn * Hh];
__device__ float g_md   [Nn];
// edge sort-by-dst structures
__device__ int g_cnt [NNODE];
__device__ int g_cur [NNODE];
__device__ int g_off [NNODE + 1];
__device__ int g_bsum[256];
__device__ int g_perm[Ee];
// transposed, bf16 hi/lo split weights
__device__ __nv_bfloat16 g_wm_h[(size_t)Ll * 2 * 256 * 256];
__device__ __nv_bfloat16 g_wm_l[(size_t)Ll * 2 * 256 * 256];
__device__ __nv_bfloat16 g_wu_h[(size_t)Ll * 256 * 512];
__device__ __nv_bfloat16 g_wu_l[(size_t)Ll * 256 * 512];

// ---------------- helpers ----------------------------------------------------
__device__ __forceinline__ uint32_t smem_u32(const void* p) {
    uint32_t a;
    asm("{ .reg .u64 t; cvta.to.shared.u64 t, %1; cvt.u32.u64 %0, t; }" : "=r"(a) : "l"(p));
    return a;
}
__device__ __forceinline__ uint32_t swz(uint32_t o) { return o ^ ((o >> 3) & 0x70); }

__device__ __forceinline__ void cpa16(uint32_t dst, const void* src) {
    asm volatile("cp.async.cg.shared.global [%0], [%1], 16;" :: "r"(dst), "l"(src));
}
#define CPCOMMIT() asm volatile("cp.async.commit_group;" ::: "memory")
#define CPWAIT0()  asm volatile("cp.async.wait_group 0;" ::: "memory")
#define CPWAIT1()  asm volatile("cp.async.wait_group 1;" ::: "memory")

#define LDSM4(r0, r1, r2, r3, a) \
    asm volatile("ldmatrix.sync.aligned.m8n8.x4.shared.b16 {%0,%1,%2,%3}, [%4];" \
        : "=r"(r0), "=r"(r1), "=r"(r2), "=r"(r3) : "r"(a))

#define MMA16816(d, a, b) \
    asm volatile("mma.sync.aligned.m16n8k16.row.col.f32.bf16.bf16.f32 " \
        "{%0,%1,%2,%3},{%4,%5,%6,%7},{%8,%9},{%0,%1,%2,%3};" \
        : "+f"((d)[0]), "+f"((d)[1]), "+f"((d)[2]), "+f"((d)[3]) \
        : "r"((a)[0]), "r"((a)[1]), "r"((a)[2]), "r"((a)[3]), "r"((b)[0]), "r"((b)[1]))

__device__ __forceinline__ void splitv(float v, __nv_bfloat16& h, __nv_bfloat16& l) {
    h = __float2bfloat16(v);
    l = __float2bfloat16(v - __bfloat162float(h));
}
__device__ __forceinline__ void split2(float a, float b, uint32_t& hi, uint32_t& lo) {
    __nv_bfloat16 ha, la, hb, lb;
    splitv(a, ha, la);
    splitv(b, hb, lb);
    hi = (uint32_t)__bfloat16_as_ushort(ha) | ((uint32_t)__bfloat16_as_ushort(hb) << 16);
    lo = (uint32_t)__bfloat16_as_ushort(la) | ((uint32_t)__bfloat16_as_ushort(lb) << 16);
}

// ---------------- weight prep -----------------------------------------------
__global__ void k_wmprep(const float* __restrict__ Wm) {
    int idx = blockIdx.x * 256 + threadIdx.x;
    int l = idx >> 17;
    int r = idx & 131071;
    int mat = r >> 16;
    int r2 = r & 65535;
    int n = r2 >> 8, k = r2 & 255;
    float v = Wm[(size_t)l * 513 * 256 + (size_t)(mat * 256 + k) * 256 + n];
    __nv_bfloat16 h, lo;
    splitv(v, h, lo);
    size_t o = ((size_t)(l * 2 + mat) * 256 + n) * 256 + k;
    g_wm_h[o] = h;
    g_wm_l[o] = lo;
}
__global__ void k_wuprep(const float* __restrict__ Wu) {
    int idx = blockIdx.x * 256 + threadIdx.x;
    int l = idx >> 17;
    int r = idx & 131071;
    int n = r >> 9, k = r & 511;
    float v = Wu[(size_t)l * 512 * 256 + (size_t)k * 256 + n];
    __nv_bfloat16 h, lo;
    splitv(v, h, lo);
    size_t o = (size_t)l * 131072 + (size_t)n * 512 + k;
    g_wu_h[o] = h;
    g_wu_l[o] = lo;
}

// ---------------- edge counting sort (by dst) -------------------------------
__global__ void k_hist0() { g_cnt[blockIdx.x * 256 + threadIdx.x] = 0; }
__global__ void k_hist(const int* __restrict__ ei) {
    int e = blockIdx.x * 256 + threadIdx.x;
    atomicAdd(&g_cnt[ei[Ee + e]], 1);
}
__global__ void k_scan1() {
    __shared__ int sh[256];
    int t = threadIdx.x, b = blockIdx.x;
    int v = g_cnt[b * 256 + t];
    sh[t] = v;
    __syncthreads();
    for (int o = 1; o < 256; o <<= 1) {
        int u = (t >= o) ? sh[t - o] : 0;
        __syncthreads();
        sh[t] += u;
        __syncthreads();
    }
    g_off[b * 256 + t] = sh[t] - v;   // exclusive within block
    if (t == 255) g_bsum[b] = sh[255];
}
__global__ void k_scan2() {
    __shared__ int sh[256];
    int t = threadIdx.x;
    int v = g_bsum[t];
    sh[t] = v;
    __syncthreads();
    for (int o = 1; o < 256; o <<= 1) {
        int u = (t >= o) ? sh[t - o] : 0;
        __syncthreads();
        sh[t] += u;
        __syncthreads();
    }
    g_bsum[t] = sh[t] - v;            // exclusive block offsets
}
__global__ void k_scan3() {
    int i = blockIdx.x * 256 + threadIdx.x;
    int v = g_off[i] + g_bsum[blockIdx.x];
    g_off[i] = v;
    g_cur[i] = v;
    if (i == 0) g_off[NNODE] = Ee;
}
__global__ void k_scatter(const int* __restrict__ ei) {
    int e = blockIdx.x * 256 + threadIdx.x;
    int d = ei[Ee + e];
    int p = atomicAdd(&g_cur[d], 1);
    g_perm[p] = e;
}

// ---------------- small prologue kernels -----------------------------------
__global__ void k_hbase(const float* __restrict__ x, const float* __restrict__ W_in,
                        const float* __restrict__ b_in) {
    __shared__ float xb[Ff];
    int b = blockIdx.x;
    if (threadIdx.x < Ff) xb[threadIdx.x] = x[b * Ff + threadIdx.x];
    __syncthreads();
    int j = threadIdx.x;
    float acc = b_in[j];
    #pragma unroll 4
    for (int k = 0; k < Ff; k++) acc = fmaf(xb[k], W_in[k * Hh + j], acc);
    g_hb[b * Hh + j] = acc;
}

__global__ void k_meand(const float* __restrict__ positions) {
    __shared__ float sp[Nn * 3];
    __shared__ float red[256];
    int i = blockIdx.x;
    for (int t = threadIdx.x; t < Nn * 3; t += 256) sp[t] = positions[t];
    __syncthreads();
    float px = sp[i * 3], py = sp[i * 3 + 1], pz = sp[i * 3 + 2];
    float sum = 0.f;
    for (int j = threadIdx.x; j < Nn; j += 256) {
        if (j == i) continue;
        float dx = px - sp[j * 3], dy = py - sp[j * 3 + 1], dz = pz - sp[j * 3 + 2];
        sum += sqrtf(dx * dx + dy * dy + dz * dz);
    }
    red[threadIdx.x] = sum;
    __syncthreads();
    for (int s = 128; s; s >>= 1) {
        if (threadIdx.x < s) red[threadIdx.x] += red[threadIdx.x + s];
        __syncthreads();
    }
    if (threadIdx.x == 0) g_md[i] = red[0] / (float)(Nn - 1);
}

__global__ void k_gfeat(const float* __restrict__ Wg1, const float* __restrict__ bg1,
                        const float* __restrict__ Wg2, const float* __restrict__ bg2) {
    __shared__ float t[Ff];
    int n = blockIdx.x;
    float m = g_md[n];
    if (threadIdx.x < 128) {
        int kk = threadIdx.x;
        float w = Wg1[kk] + Wg1[128 + kk] + Wg1[256 + kk];
        t[kk] = fmaxf(fmaf(m, w, bg1[kk]), 0.f);
    }
    __syncthreads();
    int j = threadIdx.x;
    float acc = bg2[j];
    #pragma unroll 4
    for (int kk = 0; kk < 128; kk++) acc = fmaf(t[kk], Wg2[kk * Hh + j], acc);
    g_gf[n * Hh + j] = acc;
}

__global__ void k_init(const float* __restrict__ positions) {
    int i = blockIdx.x * 256 + threadIdx.x;
    int node = i >> 8, j = i & 255;
    int b = node >> 11;
    int n = node & 2047;
    g_h0buf[i] = g_hb[b * Hh + j] + g_gf[n * Hh + j];
    if (i < NNODE * 3) {
        int nd = i / 3;
        int k = i - nd * 3;
        g_pos[i] = positions[(nd & 2047) * 3 + k];
    }
}

__global__ void k_posapply() {
    int i = blockIdx.x * 256 + threadIdx.x;
    if (i < NNODE * 3) g_pos[i] += g_pacc[i] * 0.25f;
}

// ---------------- HMMA GEMM (mma.sync bf16 split-precision) ----------------
#define MM_SMEM 131072

__global__ __launch_bounds__(256) void k_mma(
    const float* __restrict__ A0, const float* __restrict__ A1,
    const __nv_bfloat16* __restrict__ Bh, const __nv_bfloat16* __restrict__ Bl,
    int bpitch, int nchunks, int mode,
    const float* __restrict__ bias, const float* __restrict__ Xres,
    float* __restrict__ out0, float* __restrict__ out1,
    int zflags,                      // bit1: init out vector with bout
    const float* __restrict__ Wout, const float* __restrict__ bout,
    float* __restrict__ outv, int wantout)
{
    extern __shared__ char smem[];
    uint32_t sb = smem_u32(smem);
    int tid = threadIdx.x, wid = tid >> 5, lane = tid & 31;
    int row0 = blockIdx.y * 128, n0 = blockIdx.x * 128;
    int wm = wid & 3, wn = wid >> 2;

    float acc[2][8][4];
    #pragma unroll
    for (int a = 0; a < 2; a++)
        #pragma unroll
        for (int b = 0; b < 8; b++)
            #pragma unroll
            for (int c = 0; c < 4; c++) acc[a][b][c] = 0.f;

    float4 areg[8];

    auto stage_load = [&](int c) {
        const float* As = (c < 4) ? A0 : A1;
        int cb = (c & 3) * 64;
        #pragma unroll
        for (int i = 0; i < 4; i++) {
            int g = i * 256 + tid;
            int row = g >> 3, c8 = g & 7;
            const float* src = As + (size_t)(row0 + row) * 256 + cb + c8 * 8;
            areg[i * 2]     = *(const float4*)src;
            areg[i * 2 + 1] = *(const float4*)(src + 4);
        }
    };
    auto stage_store = [&](int buf) {
        #pragma unroll
        for (int i = 0; i < 4; i++) {
            int g = i * 256 + tid;
            int row = g >> 3, c8 = g & 7;
            float4 va = areg[i * 2], vb = areg[i * 2 + 1];
            uint4 hi, lo;
            split2(va.x, va.y, hi.x, lo.x);
            split2(va.z, va.w, hi.y, lo.y);
            split2(vb.x, vb.y, hi.z, lo.z);
            split2(vb.z, vb.w, hi.w, lo.w);
            uint32_t off = swz(row * 128 + c8 * 16);
            *(uint4*)(smem + buf * 65536 + off)         = hi;
            *(uint4*)(smem + buf * 65536 + 16384 + off) = lo;
        }
    };
    auto stage_b = [&](int c, int buf) {
        uint32_t base = sb + buf * 65536 + 32768;
        #pragma unroll
        for (int i = 0; i < 8; i++) {
            int g = i * 256 + tid;
            int sp = g >> 10, r = g & 1023;
            int row = r >> 3, c8 = r & 7;
            const __nv_bfloat16* src = (sp ? Bl : Bh)
                + (size_t)(n0 + row) * bpitch + c * 64 + c8 * 8;
            cpa16(base + sp * 16384 + swz(row * 128 + c8 * 16), src);
        }
        CPCOMMIT();
    };

    stage_load(0);
    stage_b(0, 0);
    stage_store(0);

    for (int c = 0; c < nchunks; c++) {
        int buf = c & 1;
        bool pf = (c + 1 < nchunks);
        if (pf) {
            stage_load(c + 1);
            stage_b(c + 1, buf ^ 1);
        }
        if (pf) CPWAIT1(); else CPWAIT0();
        __syncthreads();

        uint32_t Abase = sb + buf * 65536;
        int arow = wm * 32 + (lane & 7) + ((lane >> 3) & 1) * 8;
        int akb = ((lane >> 4) & 1) * 16;
        int brow = wn * 64 + (lane & 7) + ((lane >> 4) & 1) * 8;
        int bkb = ((lane >> 3) & 1) * 16;

        #pragma unroll
        for (int k16 = 0; k16 < 4; k16++) {
            uint32_t a_h[2][4], a_l[2][4], b_h[8][2], b_l[8][2];
            #pragma unroll
            for (int mf = 0; mf < 2; mf++) {
                uint32_t ad = Abase + swz((arow + mf * 16) * 128 + k16 * 32 + akb);
                LDSM4(a_h[mf][0], a_h[mf][1], a_h[mf][2], a_h[mf][3], ad);
                LDSM4(a_l[mf][0], a_l[mf][1], a_l[mf][2], a_l[mf][3], ad + 16384);
            }
            #pragma unroll
            for (int nf2 = 0; nf2 < 4; nf2++) {
                uint32_t bd = Abase + 32768 + swz((brow + nf2 * 16) * 128 + k16 * 32 + bkb);
                LDSM4(b_h[2 * nf2][0], b_h[2 * nf2][1],
                      b_h[2 * nf2 + 1][0], b_h[2 * nf2 + 1][1], bd);
                LDSM4(b_l[2 * nf2][0], b_l[2 * nf2][1],
                      b_l[2 * nf2 + 1][0], b_l[2 * nf2 + 1][1], bd + 16384);
            }
            #pragma unroll
            for (int mf = 0; mf < 2; mf++)
                #pragma unroll
                for (int nf = 0; nf < 8; nf++) {
                    MMA16816(acc[mf][nf], a_h[mf], b_h[nf]);
                    MMA16816(acc[mf][nf], a_h[mf], b_l[nf]);
                    MMA16816(acc[mf][nf], a_l[mf], b_h[nf]);
                }
        }
        if (pf) stage_store(buf ^ 1);
        __syncthreads();
    }

    // ---------------- epilogue ----------------
    int r_base = row0 + wm * 32 + (lane >> 2);
    int c_base = n0 + wn * 64 + 2 * (lane & 3);
    if (mode == 0) {
        #pragma unroll
        for (int mf = 0; mf < 2; mf++)
            #pragma unroll
            for (int nf = 0; nf < 8; nf++) {
                int r = r_base + mf * 16;
                int col = c_base + nf * 8;
                float* ob = (col < 256) ? out0 : out1;
                int cc = col & 255;
                *(float2*)(ob + (size_t)r * 256 + cc) =
                    make_float2(acc[mf][nf][0], acc[mf][nf][1]);
                *(float2*)(ob + (size_t)(r + 8) * 256 + cc) =
                    make_float2(acc[mf][nf][2], acc[mf][nf][3]);
            }
        if (blockIdx.x == 0 && (zflags & 2) && tid < 128) outv[row0 + tid] = bout[0];
    } else {
        float wpart[2][2] = {{0.f, 0.f}, {0.f, 0.f}};
        #pragma unroll
        for (int mf = 0; mf < 2; mf++)
            #pragma unroll
            for (int nf = 0; nf < 8; nf++) {
                int col = c_base + nf * 8;
                float b0 = bias[col], b1 = bias[col + 1];
                float w0 = 0.f, w1 = 0.f;
                if (wantout) { w0 = Wout[col]; w1 = Wout[col + 1]; }
                #pragma unroll
                for (int hr = 0; hr < 2; hr++) {
                    int r = r_base + mf * 16 + hr * 8;
                    size_t off = (size_t)r * 256 + col;
                    float2 xv = *(const float2*)(Xres + off);
                    float o0 = xv.x + fmaxf(acc[mf][nf][hr * 2]     + b0, 0.f);
                    float o1 = xv.y + fmaxf(acc[mf][nf][hr * 2 + 1] + b1, 0.f);
                    *(float2*)(out0 + off) = make_float2(o0, o1);
                    wpart[mf][hr] += o0 * w0 + o1 * w1;
                }
            }
        if (wantout) {
            #pragma unroll
            for (int mf = 0; mf < 2; mf++)
                #pragma unroll
                for (int hr = 0; hr < 2; hr++) {
                    float v = wpart[mf][hr];
                    v += __shfl_xor_sync(0xffffffffu, v, 1);
                    v += __shfl_xor_sync(0xffffffffu, v, 2);
                    if ((lane & 3) == 0)
                        atomicAdd(outv + r_base + mf * 16 + hr * 8, v);
                }
        }
    }
}

// ---------------- segmented edge kernel: 1 warp / dst node ------------------
// For dst node t: loads B[t] once, iterates its sorted edge segment,
// accumulates agg[t] and the position delta in registers, plain stores.
__global__ __launch_bounds__(256) void k_edge2(const int* __restrict__ ei,
                                               const float* __restrict__ wd,
                                               const float* __restrict__ bmv,
                                               const float* __restrict__ wp) {
    int node = (blockIdx.x << 3) + (threadIdx.x >> 5);
    int lane = threadIdx.x & 31;
    int beg = g_off[node], end = g_off[node + 1];
    int j0 = lane << 3;

    float4 w0 = *(const float4*)(wd + j0),  w1 = *(const float4*)(wd + j0 + 4);
    float4 c0 = *(const float4*)(bmv + j0), c1 = *(const float4*)(bmv + j0 + 4);
    float4 p0 = *(const float4*)(wp + j0),  p1 = *(const float4*)(wp + j0 + 4);
    const float4* B4 = (const float4*)(g_Bbuf + ((size_t)node << 8) + j0);
    float4 b0 = B4[0], b1 = B4[1];
    float ptx = g_pos[node * 3], pty = g_pos[node * 3 + 1], ptz = g_pos[node * 3 + 2];

    float4 ag0 = make_float4(0.f, 0.f, 0.f, 0.f);
    float4 ag1 = make_float4(0.f, 0.f, 0.f, 0.f);
    float pa = 0.f;   // lanes 0..2: accumulated position-delta component

    for (int i = beg; i < end; i++) {
        int e = g_perm[i];
        int s = __ldg(ei + e);
        float psx = g_pos[s * 3], psy = g_pos[s * 3 + 1], psz = g_pos[s * 3 + 2];
        float dx = psx - ptx, dy = psy - pty, dz = psz - ptz;
        float d = sqrtf(dx * dx + dy * dy + dz * dz + 1e-12f);

        const float4* A4 = (const float4*)(g_Abuf + ((size_t)s << 8) + j0);
        float4 a0 = A4[0], a1 = A4[1];

        float4 m0, m1;
        m0.x = fmaxf(fmaf(d, w0.x, a0.x + b0.x + c0.x), 0.f);
        m0.y = fmaxf(fmaf(d, w0.y, a0.y + b0.y + c0.y), 0.f);
        m0.z = fmaxf(fmaf(d, w0.z, a0.z + b0.z + c0.z), 0.f);
        m0.w = fmaxf(fmaf(d, w0.w, a0.w + b0.w + c0.w), 0.f);
        m1.x = fmaxf(fmaf(d, w1.x, a1.x + b1.x + c1.x), 0.f);
        m1.y = fmaxf(fmaf(d, w1.y, a1.y + b1.y + c1.y), 0.f);
        m1.z = fmaxf(fmaf(d, w1.z, a1.z + b1.z + c1.z), 0.f);
        m1.w = fmaxf(fmaf(d, w1.w, a1.w + b1.w + c1.w), 0.f);

        ag0.x += m0.x; ag0.y += m0.y; ag0.z += m0.z; ag0.w += m0.w;
        ag1.x += m1.x; ag1.y += m1.y; ag1.z += m1.z; ag1.w += m1.w;

        float cf = m0.x * p0.x + m0.y * p0.y + m0.z * p0.z + m0.w * p0.w
                 + m1.x * p1.x + m1.y * p1.y + m1.z * p1.z + m1.w * p1.w;
        #pragma unroll
        for (int off = 16; off; off >>= 1) cf += __shfl_xor_sync(0xffffffffu, cf, off);

        if (lane < 3) {
            float pd = (lane == 0) ? (ptx - psx) : (lane == 1) ? (pty - psy) : (ptz - psz);
            pa += pd * cf;
        }
    }

    float* ag = g_agg + ((size_t)node << 8) + j0;
    *(float4*)ag       = ag0;
    *(float4*)(ag + 4) = ag1;
    if (lane < 3) g_pacc[node * 3 + lane] = pa;
}

// ---------------- launch ----------------------------------------------------
extern "C" void kernel_launch(void* const* d_in, const int* in_sizes, int n_in,
                              void* d_out, int out_size) {
    const float* x         = (const float*)d_in[0];
    const float* positions = (const float*)d_in[1];
    const float* W_in      = (const float*)d_in[2];
    const float* b_in      = (const float*)d_in[3];
    const float* Wg1       = (const float*)d_in[4];
    const float* bg1       = (const float*)d_in[5];
    const float* Wg2       = (const float*)d_in[6];
    const float* bg2       = (const float*)d_in[7];
    const float* Wm        = (const float*)d_in[8];
    const float* bm        = (const float*)d_in[9];
    const float* Wu        = (const float*)d_in[10];
    const float* bu        = (const float*)d_in[11];
    const float* Wp        = (const float*)d_in[12];
    const float* Wout      = (const float*)d_in[13];
    const float* bout      = (const float*)d_in[14];
    const int*   ei        = (const int*)d_in[15];
    float* out = (float*)d_out;

    static float* h0 = nullptr;
    static float* h1 = nullptr;
    static float* abuf = nullptr;
    static float* bbuf = nullptr;
    static float* aggp = nullptr;
    static __nv_bfloat16 *wmh, *wml, *wuh, *wul;
    if (!h0) {
        cudaGetSymbolAddress((void**)&h0,   g_h0buf);
        cudaGetSymbolAddress((void**)&h1,   g_h1buf);
        cudaGetSymbolAddress((void**)&abuf, g_Abuf);
        cudaGetSymbolAddress((void**)&bbuf, g_Bbuf);
        cudaGetSymbolAddress((void**)&aggp, g_agg);
        cudaGetSymbolAddress((void**)&wmh,  g_wm_h);
        cudaGetSymbolAddress((void**)&wml,  g_wm_l);
        cudaGetSymbolAddress((void**)&wuh,  g_wu_h);
        cudaGetSymbolAddress((void**)&wul,  g_wu_l);
        cudaFuncSetAttribute(k_mma, cudaFuncAttributeMaxDynamicSharedMemorySize, MM_SMEM);
    }

    // prologue: weight prep, features, h init, edge sort-by-dst
    k_wmprep<<<(Ll * 2 * 65536) / 256, 256>>>(Wm);
    k_wuprep<<<(Ll * 131072) / 256, 256>>>(Wu);
    k_hbase<<<Bb, 256>>>(x, W_in, b_in);
    k_meand<<<Nn, 256>>>(positions);
    k_gfeat<<<Nn, 256>>>(Wg1, bg1, Wg2, bg2);
    k_init<<<(NNODE * Hh) / 256, 256>>>(positions);
    k_hist0<<<256, 256>>>();
    k_hist<<<Ee / 256, 256>>>(ei);
    k_scan1<<<256, 256>>>();
    k_scan2<<<1, 256>>>();
    k_scan3<<<256, 256>>>();
    k_scatter<<<Ee / 256, 256>>>(ei);

    float* hc = h0;
    float* hn = h1;
    for (int l = 0; l < Ll; l++) {
        const float* Wml = Wm + (size_t)l * 513 * 256;
        int zf = (l == Ll - 1) ? 2 : 0;
        // proj: [Abuf|Bbuf] = h @ [Wm1|Wm2]  (+out init on last layer)
        k_mma<<<dim3(4, NNODE / 128), 256, MM_SMEM>>>(
            hc, nullptr,
            wmh + (size_t)l * 2 * 65536, wml + (size_t)l * 2 * 65536,
            256, 4, 0, nullptr, nullptr, abuf, bbuf,
            zf, nullptr, bout, out, 0);
        k_edge2<<<NNODE / 8, 256>>>(ei, Wml + 512 * 256, bm + l * 256, Wp + l * 256);
        k_posapply<<<(NNODE * 3 + 255) / 256, 256>>>();
        // update: hn = h + relu(concat(h, agg) @ Wu + bu); fused GEMV on last layer
        k_mma<<<dim3(2, NNODE / 128), 256, MM_SMEM>>>(
            hc, aggp,
            wuh + (size_t)l * 131072, wul + (size_t)l * 131072,
            512, 8, 1, bu + l * 256, hc, hn, nullptr,
            0, Wout, bout, out, (l == Ll - 1) ? 1 : 0);
        float* tmp = hc; hc = hn; hn = tmp;
    }
}

// round 8
// speedup vs baseline: 2.2418x; 1.1350x over previous
#include <cuda_runtime.h>
#include <cuda_bf16.h>
#include <cstdint>

#define Bb    32
#define Ff    128
#define Hh    256
#define Nn    2048
#define Ll    2
#define Ee    262144
#define NNODE 65536   // B*N

// ---------------- scratch (device globals; no allocation allowed) ----------
__device__ float g_h1buf[(size_t)NNODE * Hh];
__device__ float g_h2buf[(size_t)NNODE * Hh];
__device__ float g_Abuf [(size_t)NNODE * Hh];
__device__ float g_Bbuf [(size_t)NNODE * Hh];
__device__ float g_agg  [(size_t)NNODE * Hh];
__device__ float g_pos  [(size_t)NNODE * 3];
__device__ float g_pacc [(size_t)NNODE * 3];
__device__ float g_hb   [Bb * Hh];
__device__ float g_gf   [Nn * Hh];
__device__ float g_md   [Nn];
// low-rank layer-0 products: P[r][0:256]=h@Wm1, [256:512]=h@Wm2, [512:768]=h@Wu[0:256]
// rows: 0..31 = hb, 32..2079 = gf
__device__ float g_P[(size_t)2080 * 768];
// edge sort-by-dst structures
__device__ int g_cnt [NNODE];
__device__ int g_cur [NNODE];
__device__ int g_off [NNODE + 1];
__device__ int g_bsum[256];
__device__ int g_perm[Ee];
// transposed, bf16 hi/lo split weights
__device__ __nv_bfloat16 g_wm_h[(size_t)Ll * 2 * 256 * 256];
__device__ __nv_bfloat16 g_wm_l[(size_t)Ll * 2 * 256 * 256];
__device__ __nv_bfloat16 g_wu_h[(size_t)Ll * 256 * 512];
__device__ __nv_bfloat16 g_wu_l[(size_t)Ll * 256 * 512];

// ---------------- helpers ----------------------------------------------------
__device__ __forceinline__ uint32_t smem_u32(const void* p) {
    uint32_t a;
    asm("{ .reg .u64 t; cvta.to.shared.u64 t, %1; cvt.u32.u64 %0, t; }" : "=r"(a) : "l"(p));
    return a;
}
__device__ __forceinline__ uint32_t swz(uint32_t o) { return o ^ ((o >> 3) & 0x70); }

__device__ __forceinline__ void cpa16(uint32_t dst, const void* src) {
    asm volatile("cp.async.cg.shared.global [%0], [%1], 16;" :: "r"(dst), "l"(src));
}
#define CPCOMMIT() asm volatile("cp.async.commit_group;" ::: "memory")
#define CPWAIT0()  asm volatile("cp.async.wait_group 0;" ::: "memory")
#define CPWAIT1()  asm volatile("cp.async.wait_group 1;" ::: "memory")

#define LDSM4(r0, r1, r2, r3, a) \
    asm volatile("ldmatrix.sync.aligned.m8n8.x4.shared.b16 {%0,%1,%2,%3}, [%4];" \
        : "=r"(r0), "=r"(r1), "=r"(r2), "=r"(r3) : "r"(a))

#define MMA16816(d, a, b) \
    asm volatile("mma.sync.aligned.m16n8k16.row.col.f32.bf16.bf16.f32 " \
        "{%0,%1,%2,%3},{%4,%5,%6,%7},{%8,%9},{%0,%1,%2,%3};" \
        : "+f"((d)[0]), "+f"((d)[1]), "+f"((d)[2]), "+f"((d)[3]) \
        : "r"((a)[0]), "r"((a)[1]), "r"((a)[2]), "r"((a)[3]), "r"((b)[0]), "r"((b)[1]))

__device__ __forceinline__ void splitv(float v, __nv_bfloat16& h, __nv_bfloat16& l) {
    h = __float2bfloat16(v);
    l = __float2bfloat16(v - __bfloat162float(h));
}
__device__ __forceinline__ void split2(float a, float b, uint32_t& hi, uint32_t& lo) {
    __nv_bfloat16 ha, la, hb, lb;
    splitv(a, ha, la);
    splitv(b, hb, lb);
    hi = (uint32_t)__bfloat16_as_ushort(ha) | ((uint32_t)__bfloat16_as_ushort(hb) << 16);
    lo = (uint32_t)__bfloat16_as_ushort(la) | ((uint32_t)__bfloat16_as_ushort(lb) << 16);
}

// ---------------- weight prep -----------------------------------------------
__global__ void k_wmprep(const float* __restrict__ Wm) {
    int idx = blockIdx.x * 256 + threadIdx.x;
    int l = idx >> 17;
    int r = idx & 131071;
    int mat = r >> 16;
    int r2 = r & 65535;
    int n = r2 >> 8, k = r2 & 255;
    float v = Wm[(size_t)l * 513 * 256 + (size_t)(mat * 256 + k) * 256 + n];
    __nv_bfloat16 h, lo;
    splitv(v, h, lo);
    size_t o = ((size_t)(l * 2 + mat) * 256 + n) * 256 + k;
    g_wm_h[o] = h;
    g_wm_l[o] = lo;
}
__global__ void k_wuprep(const float* __restrict__ Wu) {
    int idx = blockIdx.x * 256 + threadIdx.x;
    int l = idx >> 17;
    int r = idx & 131071;
    int n = r >> 9, k = r & 511;
    float v = Wu[(size_t)l * 512 * 256 + (size_t)k * 256 + n];
    __nv_bfloat16 h, lo;
    splitv(v, h, lo);
    size_t o = (size_t)l * 131072 + (size_t)n * 512 + k;
    g_wu_h[o] = h;
    g_wu_l[o] = lo;
}

// ---------------- edge counting sort (by dst) -------------------------------
__global__ void k_hist0() { g_cnt[blockIdx.x * 256 + threadIdx.x] = 0; }
__global__ void k_hist(const int* __restrict__ ei) {
    int e = blockIdx.x * 256 + threadIdx.x;
    atomicAdd(&g_cnt[ei[Ee + e]], 1);
}
__global__ void k_scan1() {
    __shared__ int sh[256];
    int t = threadIdx.x, b = blockIdx.x;
    int v = g_cnt[b * 256 + t];
    sh[t] = v;
    __syncthreads();
    for (int o = 1; o < 256; o <<= 1) {
        int u = (t >= o) ? sh[t - o] : 0;
        __syncthreads();
        sh[t] += u;
        __syncthreads();
    }
    g_off[b * 256 + t] = sh[t] - v;
    if (t == 255) g_bsum[b] = sh[255];
}
__global__ void k_scan2() {
    __shared__ int sh[256];
    int t = threadIdx.x;
    int v = g_bsum[t];
    sh[t] = v;
    __syncthreads();
    for (int o = 1; o < 256; o <<= 1) {
        int u = (t >= o) ? sh[t - o] : 0;
        __syncthreads();
        sh[t] += u;
        __syncthreads();
    }
    g_bsum[t] = sh[t] - v;
}
__global__ void k_scan3() {
    int i = blockIdx.x * 256 + threadIdx.x;
    int v = g_off[i] + g_bsum[blockIdx.x];
    g_off[i] = v;
    g_cur[i] = v;
    if (i == 0) g_off[NNODE] = Ee;
}
__global__ void k_scatter(const int* __restrict__ ei) {
    int e = blockIdx.x * 256 + threadIdx.x;
    int d = ei[Ee + e];
    int p = atomicAdd(&g_cur[d], 1);
    g_perm[p] = e;
}

// ---------------- small prologue kernels -----------------------------------
__global__ void k_hbase(const float* __restrict__ x, const float* __restrict__ W_in,
                        const float* __restrict__ b_in) {
    __shared__ float xb[Ff];
    int b = blockIdx.x;
    if (threadIdx.x < Ff) xb[threadIdx.x] = x[b * Ff + threadIdx.x];
    __syncthreads();
    int j = threadIdx.x;
    float acc = b_in[j];
    #pragma unroll 4
    for (int k = 0; k < Ff; k++) acc = fmaf(xb[k], W_in[k * Hh + j], acc);
    g_hb[b * Hh + j] = acc;
}

__global__ void k_meand(const float* __restrict__ positions) {
    __shared__ float sp[Nn * 3];
    __shared__ float red[256];
    int i = blockIdx.x;
    for (int t = threadIdx.x; t < Nn * 3; t += 256) sp[t] = positions[t];
    __syncthreads();
    float px = sp[i * 3], py = sp[i * 3 + 1], pz = sp[i * 3 + 2];
    float sum = 0.f;
    for (int j = threadIdx.x; j < Nn; j += 256) {
        if (j == i) continue;
        float dx = px - sp[j * 3], dy = py - sp[j * 3 + 1], dz = pz - sp[j * 3 + 2];
        sum += sqrtf(dx * dx + dy * dy + dz * dz);
    }
    red[threadIdx.x] = sum;
    __syncthreads();
    for (int s = 128; s; s >>= 1) {
        if (threadIdx.x < s) red[threadIdx.x] += red[threadIdx.x + s];
        __syncthreads();
    }
    if (threadIdx.x == 0) g_md[i] = red[0] / (float)(Nn - 1);
}

__global__ void k_gfeat(const float* __restrict__ Wg1, const float* __restrict__ bg1,
                        const float* __restrict__ Wg2, const float* __restrict__ bg2) {
    __shared__ float t[Ff];
    int n = blockIdx.x;
    float m = g_md[n];
    if (threadIdx.x < 128) {
        int kk = threadIdx.x;
        float w = Wg1[kk] + Wg1[128 + kk] + Wg1[256 + kk];
        t[kk] = fmaxf(fmaf(m, w, bg1[kk]), 0.f);
    }
    __syncthreads();
    int j = threadIdx.x;
    float acc = bg2[j];
    #pragma unroll 4
    for (int kk = 0; kk < 128; kk++) acc = fmaf(t[kk], Wg2[kk * Hh + j], acc);
    g_gf[n * Hh + j] = acc;
}

// pos broadcast only (h0 never materialized)
__global__ void k_initpos(const float* __restrict__ positions) {
    int i = blockIdx.x * 256 + threadIdx.x;
    if (i < NNODE * 3) {
        int nd = i / 3;
        int k = i - nd * 3;
        g_pos[i] = positions[(nd & 2047) * 3 + k];
    }
}

__global__ void k_posapply() {
    int i = blockIdx.x * 256 + threadIdx.x;
    if (i < NNODE * 3) g_pos[i] += g_pacc[i] * 0.25f;
}

// ---------------- low-rank layer-0 small GEMM -------------------------------
// P[r][j]     = hrow(r) . Wm_L0_mat1[:, j]
// P[r][256+j] = hrow(r) . Wm_L0_mat2[:, j]
// P[r][512+j] = hrow(r) . Wu_L0[0:256, j]
// 130 blocks x 16 rows; 256 threads = one column j each.
__global__ __launch_bounds__(256) void k_small(const float* __restrict__ Wm,
                                               const float* __restrict__ Wu) {
    __shared__ float hs[16][257];
    int r0 = blockIdx.x * 16;
    int tid = threadIdx.x;
    for (int i = 0; i < 16; i++) {
        int r = r0 + i;
        const float* src = (r < 32) ? (g_hb + r * 256) : (g_gf + (size_t)(r - 32) * 256);
        hs[i][tid] = src[tid];
    }
    __syncthreads();
    float a1[16], a2[16], a3[16];
    #pragma unroll
    for (int i = 0; i < 16; i++) { a1[i] = 0.f; a2[i] = 0.f; a3[i] = 0.f; }
    for (int k = 0; k < 256; k++) {
        float w1 = Wm[(size_t)k * 256 + tid];
        float w2 = Wm[(size_t)(256 + k) * 256 + tid];
        float w3 = Wu[(size_t)k * 256 + tid];
        #pragma unroll
        for (int i = 0; i < 16; i++) {
            float hv = hs[i][k];
            a1[i] = fmaf(hv, w1, a1[i]);
            a2[i] = fmaf(hv, w2, a2[i]);
            a3[i] = fmaf(hv, w3, a3[i]);
        }
    }
    #pragma unroll
    for (int i = 0; i < 16; i++) {
        size_t o = (size_t)(r0 + i) * 768;
        g_P[o + tid]       = a1[i];
        g_P[o + 256 + tid] = a2[i];
        g_P[o + 512 + tid] = a3[i];
    }
}

// combine: Abuf[r][j] = P[b][j] + P[32+n][j]; Bbuf[r][j] = P[b][256+j] + P[32+n][256+j]
__global__ __launch_bounds__(256) void k_combine() {
    int idx = blockIdx.x * 256 + threadIdx.x;   // NNODE*128 float4 slots
    int r = idx >> 7, q = idx & 127;            // q: float4 index over 512 cols
    int b = r >> 11, n = r & 2047;
    const float4* pb = (const float4*)(g_P + (size_t)b * 768);
    const float4* pg = (const float4*)(g_P + (size_t)(32 + n) * 768);
    float4 vb = pb[q], vg = pg[q];
    float4 v = make_float4(vb.x + vg.x, vb.y + vg.y, vb.z + vg.z, vb.w + vg.w);
    float* ob = (q < 64) ? g_Abuf : g_Bbuf;
    ((float4*)(ob + (size_t)r * 256))[q & 63] = v;
}

// ---------------- HMMA GEMM (mma.sync bf16 split-precision) ----------------
// mode 0: proj store (col<256 -> out0, else out1); zflags bit1: init outv=bout.
// mode 1: out0 = Xres + relu(C + bias); wantout: fused GEMV into outv.
// mode 2: layer-0 update: out0 = (hb[b]+gf[n]) + relu(C + Pu[b]+Pu[n] + bias).
#define MM_SMEM 131072

__global__ __launch_bounds__(256) void k_mma(
    const float* __restrict__ A0, const float* __restrict__ A1,
    const __nv_bfloat16* __restrict__ Bh, const __nv_bfloat16* __restrict__ Bl,
    int bpitch, int cstart, int nchunks, int mode,
    const float* __restrict__ bias, const float* __restrict__ Xres,
    float* __restrict__ out0, float* __restrict__ out1,
    int zflags,
    const float* __restrict__ Wout, const float* __restrict__ bout,
    float* __restrict__ outv, int wantout)
{
    extern __shared__ char smem[];
    uint32_t sb = smem_u32(smem);
    int tid = threadIdx.x, wid = tid >> 5, lane = tid & 31;
    int row0 = blockIdx.y * 128, n0 = blockIdx.x * 128;
    int wm = wid & 3, wn = wid >> 2;

    float acc[2][8][4];
    #pragma unroll
    for (int a = 0; a < 2; a++)
        #pragma unroll
        for (int b = 0; b < 8; b++)
            #pragma unroll
            for (int c = 0; c < 4; c++) acc[a][b][c] = 0.f;

    float4 areg[8];

    auto stage_load = [&](int c) {
        const float* As = (c < 4) ? A0 : A1;
        int cb = (c & 3) * 64;
        #pragma unroll
        for (int i = 0; i < 4; i++) {
            int g = i * 256 + tid;
            int row = g >> 3, c8 = g & 7;
            const float* src = As + (size_t)(row0 + row) * 256 + cb + c8 * 8;
            areg[i * 2]     = *(const float4*)src;
            areg[i * 2 + 1] = *(const float4*)(src + 4);
        }
    };
    auto stage_store = [&](int buf) {
        #pragma unroll
        for (int i = 0; i < 4; i++) {
            int g = i * 256 + tid;
            int row = g >> 3, c8 = g & 7;
            float4 va = areg[i * 2], vb = areg[i * 2 + 1];
            uint4 hi, lo;
            split2(va.x, va.y, hi.x, lo.x);
            split2(va.z, va.w, hi.y, lo.y);
            split2(vb.x, vb.y, hi.z, lo.z);
            split2(vb.z, vb.w, hi.w, lo.w);
            uint32_t off = swz(row * 128 + c8 * 16);
            *(uint4*)(smem + buf * 65536 + off)         = hi;
            *(uint4*)(smem + buf * 65536 + 16384 + off) = lo;
        }
    };
    auto stage_b = [&](int c, int buf) {
        uint32_t base = sb + buf * 65536 + 32768;
        #pragma unroll
        for (int i = 0; i < 8; i++) {
            int g = i * 256 + tid;
            int sp = g >> 10, r = g & 1023;
            int row = r >> 3, c8 = r & 7;
            const __nv_bfloat16* src = (sp ? Bl : Bh)
                + (size_t)(n0 + row) * bpitch + c * 64 + c8 * 8;
            cpa16(base + sp * 16384 + swz(row * 128 + c8 * 16), src);
        }
        CPCOMMIT();
    };

    stage_load(cstart);
    stage_b(cstart, cstart & 1);
    stage_store(cstart & 1);

    for (int c = cstart; c < nchunks; c++) {
        int buf = c & 1;
        bool pf = (c + 1 < nchunks);
        if (pf) {
            stage_load(c + 1);
            stage_b(c + 1, buf ^ 1);
        }
        if (pf) CPWAIT1(); else CPWAIT0();
        __syncthreads();

        uint32_t Abase = sb + buf * 65536;
        int arow = wm * 32 + (lane & 7) + ((lane >> 3) & 1) * 8;
        int akb = ((lane >> 4) & 1) * 16;
        int brow = wn * 64 + (lane & 7) + ((lane >> 4) & 1) * 8;
        int bkb = ((lane >> 3) & 1) * 16;

        #pragma unroll
        for (int k16 = 0; k16 < 4; k16++) {
            uint32_t a_h[2][4], a_l[2][4], b_h[8][2], b_l[8][2];
            #pragma unroll
            for (int mf = 0; mf < 2; mf++) {
                uint32_t ad = Abase + swz((arow + mf * 16) * 128 + k16 * 32 + akb);
                LDSM4(a_h[mf][0], a_h[mf][1], a_h[mf][2], a_h[mf][3], ad);
                LDSM4(a_l[mf][0], a_l[mf][1], a_l[mf][2], a_l[mf][3], ad + 16384);
            }
            #pragma unroll
            for (int nf2 = 0; nf2 < 4; nf2++) {
                uint32_t bd = Abase + 32768 + swz((brow + nf2 * 16) * 128 + k16 * 32 + bkb);
                LDSM4(b_h[2 * nf2][0], b_h[2 * nf2][1],
                      b_h[2 * nf2 + 1][0], b_h[2 * nf2 + 1][1], bd);
                LDSM4(b_l[2 * nf2][0], b_l[2 * nf2][1],
                      b_l[2 * nf2 + 1][0], b_l[2 * nf2 + 1][1], bd + 16384);
            }
            #pragma unroll
            for (int mf = 0; mf < 2; mf++)
                #pragma unroll
                for (int nf = 0; nf < 8; nf++) {
                    MMA16816(acc[mf][nf], a_h[mf], b_h[nf]);
                    MMA16816(acc[mf][nf], a_h[mf], b_l[nf]);
                    MMA16816(acc[mf][nf], a_l[mf], b_h[nf]);
                }
        }
        if (pf) stage_store(buf ^ 1);
        __syncthreads();
    }

    // ---------------- epilogue ----------------
    int r_base = row0 + wm * 32 + (lane >> 2);
    int c_base = n0 + wn * 64 + 2 * (lane & 3);
    if (mode == 0) {
        #pragma unroll
        for (int mf = 0; mf < 2; mf++)
            #pragma unroll
            for (int nf = 0; nf < 8; nf++) {
                int r = r_base + mf * 16;
                int col = c_base + nf * 8;
                float* ob = (col < 256) ? out0 : out1;
                int cc = col & 255;
                *(float2*)(ob + (size_t)r * 256 + cc) =
                    make_float2(acc[mf][nf][0], acc[mf][nf][1]);
                *(float2*)(ob + (size_t)(r + 8) * 256 + cc) =
                    make_float2(acc[mf][nf][2], acc[mf][nf][3]);
            }
        if (blockIdx.x == 0 && (zflags & 2) && tid < 128) outv[row0 + tid] = bout[0];
    } else if (mode == 1) {
        float wpart[2][2] = {{0.f, 0.f}, {0.f, 0.f}};
        #pragma unroll
        for (int mf = 0; mf < 2; mf++)
            #pragma unroll
            for (int nf = 0; nf < 8; nf++) {
                int col = c_base + nf * 8;
                float b0 = bias[col], b1 = bias[col + 1];
                float w0 = 0.f, w1 = 0.f;
                if (wantout) { w0 = Wout[col]; w1 = Wout[col + 1]; }
                #pragma unroll
                for (int hr = 0; hr < 2; hr++) {
                    int r = r_base + mf * 16 + hr * 8;
                    size_t off = (size_t)r * 256 + col;
                    float2 xv = *(const float2*)(Xres + off);
                    float o0 = xv.x + fmaxf(acc[mf][nf][hr * 2]     + b0, 0.f);
                    float o1 = xv.y + fmaxf(acc[mf][nf][hr * 2 + 1] + b1, 0.f);
                    *(float2*)(out0 + off) = make_float2(o0, o1);
                    wpart[mf][hr] += o0 * w0 + o1 * w1;
                }
            }
        if (wantout) {
            #pragma unroll
            for (int mf = 0; mf < 2; mf++)
                #pragma unroll
                for (int hr = 0; hr < 2; hr++) {
                    float v = wpart[mf][hr];
                    v += __shfl_xor_sync(0xffffffffu, v, 1);
                    v += __shfl_xor_sync(0xffffffffu, v, 2);
                    if ((lane & 3) == 0)
                        atomicAdd(outv + r_base + mf * 16 + hr * 8, v);
                }
        }
    } else {
        // mode 2: layer-0 update. C covers agg part only; add low-rank h-part.
        #pragma unroll
        for (int mf = 0; mf < 2; mf++)
            #pragma unroll
            for (int nf = 0; nf < 8; nf++) {
                int col = c_base + nf * 8;
                float b0 = bias[col], b1 = bias[col + 1];
                #pragma unroll
                for (int hr = 0; hr < 2; hr++) {
                    int r = r_base + mf * 16 + hr * 8;
                    int bb = r >> 11, nn = r & 2047;
                    const float* hbr = g_hb + bb * 256 + col;
                    const float* gfr = g_gf + (size_t)nn * 256 + col;
                    const float* phr = g_P + (size_t)bb * 768 + 512 + col;
                    const float* pgr = g_P + (size_t)(32 + nn) * 768 + 512 + col;
                    float x0 = hbr[0] + gfr[0];
                    float x1 = hbr[1] + gfr[1];
                    float ci0 = phr[0] + pgr[0];
                    float ci1 = phr[1] + pgr[1];
                    float o0 = x0 + fmaxf(acc[mf][nf][hr * 2]     + ci0 + b0, 0.f);
                    float o1 = x1 + fmaxf(acc[mf][nf][hr * 2 + 1] + ci1 + b1, 0.f);
                    *(float2*)(out0 + (size_t)r * 256 + col) = make_float2(o0, o1);
                }
            }
    }
}

// ---------------- segmented edge kernel: 1 warp / dst node ------------------
__global__ __launch_bounds__(256) void k_edge2(const int* __restrict__ ei,
                                               const float* __restrict__ wd,
                                               const float* __restrict__ bmv,
                                               const float* __restrict__ wp) {
    int node = (blockIdx.x << 3) + (threadIdx.x >> 5);
    int lane = threadIdx.x & 31;
    int beg = g_off[node], end = g_off[node + 1];
    int j0 = lane << 3;

    float4 w0 = *(const float4*)(wd + j0),  w1 = *(const float4*)(wd + j0 + 4);
    float4 c0 = *(const float4*)(bmv + j0), c1 = *(const float4*)(bmv + j0 + 4);
    float4 p0 = *(const float4*)(wp + j0),  p1 = *(const float4*)(wp + j0 + 4);
    const float4* B4 = (const float4*)(g_Bbuf + ((size_t)node << 8) + j0);
    float4 b0 = B4[0], b1 = B4[1];
    float ptx = g_pos[node * 3], pty = g_pos[node * 3 + 1], ptz = g_pos[node * 3 + 2];

    float4 ag0 = make_float4(0.f, 0.f, 0.f, 0.f);
    float4 ag1 = make_float4(0.f, 0.f, 0.f, 0.f);
    float pa = 0.f;

    for (int i = beg; i < end; i++) {
        int e = g_perm[i];
        int s = __ldg(ei + e);
        float psx = g_pos[s * 3], psy = g_pos[s * 3 + 1], psz = g_pos[s * 3 + 2];
        float dx = psx - ptx, dy = psy - pty, dz = psz - ptz;
        float d = sqrtf(dx * dx + dy * dy + dz * dz + 1e-12f);

        const float4* A4 = (const float4*)(g_Abuf + ((size_t)s << 8) + j0);
        float4 a0 = A4[0], a1 = A4[1];

        float4 m0, m1;
        m0.x = fmaxf(fmaf(d, w0.x, a0.x + b0.x + c0.x), 0.f);
        m0.y = fmaxf(fmaf(d, w0.y, a0.y + b0.y + c0.y), 0.f);
        m0.z = fmaxf(fmaf(d, w0.z, a0.z + b0.z + c0.z), 0.f);
        m0.w = fmaxf(fmaf(d, w0.w, a0.w + b0.w + c0.w), 0.f);
        m1.x = fmaxf(fmaf(d, w1.x, a1.x + b1.x + c1.x), 0.f);
        m1.y = fmaxf(fmaf(d, w1.y, a1.y + b1.y + c1.y), 0.f);
        m1.z = fmaxf(fmaf(d, w1.z, a1.z + b1.z + c1.z), 0.f);
        m1.w = fmaxf(fmaf(d, w1.w, a1.w + b1.w + c1.w), 0.f);

        ag0.x += m0.x; ag0.y += m0.y; ag0.z += m0.z; ag0.w += m0.w;
        ag1.x += m1.x; ag1.y += m1.y; ag1.z += m1.z; ag1.w += m1.w;

        float cf = m0.x * p0.x + m0.y * p0.y + m0.z * p0.z + m0.w * p0.w
                 + m1.x * p1.x + m1.y * p1.y + m1.z * p1.z + m1.w * p1.w;
        #pragma unroll
        for (int off = 16; off; off >>= 1) cf += __shfl_xor_sync(0xffffffffu, cf, off);

        if (lane < 3) {
            float pd = (lane == 0) ? (ptx - psx) : (lane == 1) ? (pty - psy) : (ptz - psz);
            pa += pd * cf;
        }
    }

    float* ag = g_agg + ((size_t)node << 8) + j0;
    *(float4*)ag       = ag0;
    *(float4*)(ag + 4) = ag1;
    if (lane < 3) g_pacc[node * 3 + lane] = pa;
}

// ---------------- launch ----------------------------------------------------
extern "C" void kernel_launch(void* const* d_in, const int* in_sizes, int n_in,
                              void* d_out, int out_size) {
    const float* x         = (const float*)d_in[0];
    const float* positions = (const float*)d_in[1];
    const float* W_in      = (const float*)d_in[2];
    const float* b_in      = (const float*)d_in[3];
    const float* Wg1       = (const float*)d_in[4];
    const float* bg1       = (const float*)d_in[5];
    const float* Wg2       = (const float*)d_in[6];
    const float* bg2       = (const float*)d_in[7];
    const float* Wm        = (const float*)d_in[8];
    const float* bm        = (const float*)d_in[9];
    const float* Wu        = (const float*)d_in[10];
    const float* bu        = (const float*)d_in[11];
    const float* Wp        = (const float*)d_in[12];
    const float* Wout      = (const float*)d_in[13];
    const float* bout      = (const float*)d_in[14];
    const int*   ei        = (const int*)d_in[15];
    float* out = (float*)d_out;

    static float* h1 = nullptr;
    static float* h2 = nullptr;
    static float* abuf = nullptr;
    static float* bbuf = nullptr;
    static float* aggp = nullptr;
    static __nv_bfloat16 *wmh, *wml, *wuh, *wul;
    if (!h1) {
        cudaGetSymbolAddress((void**)&h1,   g_h1buf);
        cudaGetSymbolAddress((void**)&h2,   g_h2buf);
        cudaGetSymbolAddress((void**)&abuf, g_Abuf);
        cudaGetSymbolAddress((void**)&bbuf, g_Bbuf);
        cudaGetSymbolAddress((void**)&aggp, g_agg);
        cudaGetSymbolAddress((void**)&wmh,  g_wm_h);
        cudaGetSymbolAddress((void**)&wml,  g_wm_l);
        cudaGetSymbolAddress((void**)&wuh,  g_wu_h);
        cudaGetSymbolAddress((void**)&wul,  g_wu_l);
        cudaFuncSetAttribute(k_mma, cudaFuncAttributeMaxDynamicSharedMemorySize, MM_SMEM);
    }

    // prologue
    k_wmprep<<<(Ll * 2 * 65536) / 256, 256>>>(Wm);
    k_wuprep<<<(Ll * 131072) / 256, 256>>>(Wu);
    k_hbase<<<Bb, 256>>>(x, W_in, b_in);
    k_meand<<<Nn, 256>>>(positions);
    k_gfeat<<<Nn, 256>>>(Wg1, bg1, Wg2, bg2);
    k_initpos<<<(NNODE * 3 + 255) / 256, 256>>>(positions);
    k_hist0<<<256, 256>>>();
    k_hist<<<Ee / 256, 256>>>(ei);
    k_scan1<<<256, 256>>>();
    k_scan2<<<1, 256>>>();
    k_scan3<<<256, 256>>>();
    k_scatter<<<Ee / 256, 256>>>(ei);

    // ---- layer 0 (low-rank h0 path) ----
    k_small<<<130, 256>>>(Wm, Wu);
    k_combine<<<(NNODE * 128) / 256, 256>>>();
    k_edge2<<<NNODE / 8, 256>>>(ei, Wm + 512 * 256, bm, Wp);
    k_posapply<<<(NNODE * 3 + 255) / 256, 256>>>();
    // update-L0: h1 = (hb+gf) + relu(agg@Wu[256:512] + Pu + bu)   [mode 2]
    k_mma<<<dim3(2, NNODE / 128), 256, MM_SMEM>>>(
        nullptr, aggp, wuh, wul, 512, 4, 8, 2,
        bu, nullptr, h1, nullptr, 0, nullptr, nullptr, nullptr, 0);

    // ---- layer 1 (full-rank) ----
    const float* Wml = Wm + (size_t)513 * 256;
    k_mma<<<dim3(4, NNODE / 128), 256, MM_SMEM>>>(
        h1, nullptr, wmh + (size_t)2 * 65536, wml + (size_t)2 * 65536,
        256, 0, 4, 0, nullptr, nullptr, abuf, bbuf,
        2, nullptr, bout, out, 0);
    k_edge2<<<NNODE / 8, 256>>>(ei, Wml + 512 * 256, bm + 256, Wp + 256);
    k_posapply<<<(NNODE * 3 + 255) / 256, 256>>>();
    k_mma<<<dim3(2, NNODE / 128), 256, MM_SMEM>>>(
        h1, aggp, wuh + 131072, wul + 131072, 512, 0, 8, 1,
        bu + 256, h1, h2, nullptr, 0, Wout, bout, out, 1);
}